// round 14
// baseline (speedup 1.0000x reference)
#include <cuda_runtime.h>
#include <cuda_bf16.h>
#include <math.h>
#include <cstdint>

#define B_   4
#define LQ_  2048
#define LK_  2048
#define IND  1024
#define NH_  16
#define HD_  64
#define HDA  1024
#define NZ   (B_*NH_)
#define NEGV (-1e9f)

typedef unsigned long long u64;

// Scratch (device globals)
__device__ __nv_bfloat16 g_Xhi[(size_t)B_ * LQ_ * IND];
__device__ __nv_bfloat16 g_Xlo[(size_t)B_ * LQ_ * IND];
__device__ __nv_bfloat16 g_Whi[(size_t)IND * IND];
__device__ __nv_bfloat16 g_Wlo[(size_t)IND * IND];
__device__ __nv_bfloat16 g_Qhi[(size_t)NZ * LQ_ * HD_];
__device__ __nv_bfloat16 g_Qlo[(size_t)NZ * LQ_ * HD_];
__device__ __nv_bfloat16 g_Khi[(size_t)NZ * LK_ * HD_];
__device__ __nv_bfloat16 g_Klo[(size_t)NZ * LK_ * HD_];
__device__ __nv_bfloat16 g_Vthi[(size_t)NZ * HD_ * LK_];
__device__ __nv_bfloat16 g_Vtlo[(size_t)NZ * HD_ * LK_];
__device__ float  g_Vf[(size_t)NZ * LK_ * HD_];
__device__ float  g_Oh[(size_t)B_ * LQ_ * HDA];
__device__ float2 g_part[(size_t)NZ * 16 * LQ_];
__device__ float2 g_stats[(size_t)NZ * LQ_];

// ---------------- helpers ----------------
__device__ __forceinline__ u64 pack2(float x, float y) {
    u64 r; asm("mov.b64 %0, {%1, %2};" : "=l"(r) : "f"(x), "f"(y)); return r;
}
__device__ __forceinline__ float2 unpack2(u64 v) {
    float x, y; asm("mov.b64 {%0, %1}, %2;" : "=f"(x), "=f"(y) : "l"(v));
    return make_float2(x, y);
}
__device__ __forceinline__ u64 ffma2(u64 a, u64 b, u64 c) {
    u64 d; asm("fma.rn.f32x2 %0, %1, %2, %3;" : "=l"(d) : "l"(a), "l"(b), "l"(c));
    return d;
}
__device__ __forceinline__ uint32_t smem_u32(const void* p) {
    uint32_t a;
    asm("{ .reg .u64 t; cvta.to.shared.u64 t, %1; cvt.u32.u64 %0, t; }" : "=r"(a) : "l"(p));
    return a;
}
__device__ __forceinline__ void cpa16(uint32_t dst, const void* src) {
    asm volatile("cp.async.cg.shared.global [%0], [%1], 16;" :: "r"(dst), "l"(src));
}
#define CP_COMMIT() asm volatile("cp.async.commit_group;" ::: "memory")
#define CP_WAIT0()  asm volatile("cp.async.wait_group 0;" ::: "memory")
#define CP_WAIT1()  asm volatile("cp.async.wait_group 1;" ::: "memory")

__device__ __forceinline__ void ldsm4(uint32_t (&r)[4], uint32_t addr) {
    asm volatile("ldmatrix.sync.aligned.m8n8.x4.shared.b16 {%0,%1,%2,%3}, [%4];"
                 : "=r"(r[0]), "=r"(r[1]), "=r"(r[2]), "=r"(r[3]) : "r"(addr));
}
__device__ __forceinline__ uint32_t fa72(uint32_t base, int row0, int k0, int lane) {
    const int g = lane >> 3;
    const int row = row0 + (lane & 7) + ((g & 1) << 3);
    const int col = k0 + ((g >> 1) << 3);
    return base + (uint32_t)(row * 72 + col) * 2;
}
__device__ __forceinline__ uint32_t fa40(uint32_t base, int row0, int k0, int lane) {
    const int g = lane >> 3;
    const int row = row0 + (lane & 7) + ((g & 1) << 3);
    const int col = k0 + ((g >> 1) << 3);
    return base + (uint32_t)(row * 40 + col) * 2;
}
__device__ __forceinline__ void mma16816(float (&d)[4], const uint32_t (&a)[4],
                                         uint32_t b0, uint32_t b1) {
    asm volatile(
        "mma.sync.aligned.m16n8k16.row.col.f32.bf16.bf16.f32 "
        "{%0,%1,%2,%3},{%4,%5,%6,%7},{%8,%9},{%0,%1,%2,%3};"
        : "+f"(d[0]), "+f"(d[1]), "+f"(d[2]), "+f"(d[3])
        : "r"(a[0]), "r"(a[1]), "r"(a[2]), "r"(a[3]), "r"(b0), "r"(b1));
}
__device__ __forceinline__ void split8(const float* v, uint4& hi, uint4& lo) {
    unsigned short h[8], l[8];
    #pragma unroll
    for (int i = 0; i < 8; i++) {
        __nv_bfloat16 hb = __float2bfloat16_rn(v[i]);
        __nv_bfloat16 lb = __float2bfloat16_rn(v[i] - __bfloat162float(hb));
        h[i] = __bfloat16_as_ushort(hb);
        l[i] = __bfloat16_as_ushort(lb);
    }
    hi.x = h[0] | ((uint32_t)h[1] << 16); hi.y = h[2] | ((uint32_t)h[3] << 16);
    hi.z = h[4] | ((uint32_t)h[5] << 16); hi.w = h[6] | ((uint32_t)h[7] << 16);
    lo.x = l[0] | ((uint32_t)l[1] << 16); lo.y = l[2] | ((uint32_t)l[3] << 16);
    lo.z = l[4] | ((uint32_t)l[5] << 16); lo.w = l[6] | ((uint32_t)l[7] << 16);
}

// ---------------------------------------------------------------------------
// Split fp32 -> bf16 hi/lo (streaming).
// ---------------------------------------------------------------------------
__global__ __launch_bounds__(256) void split_kernel(
    const float* __restrict__ x, __nv_bfloat16* __restrict__ hi,
    __nv_bfloat16* __restrict__ lo, int n8)
{
    const int i = blockIdx.x * 256 + threadIdx.x;
    if (i >= n8) return;
    float v[8];
    *(float4*)v       = *(const float4*)(x + (size_t)i * 8);
    *(float4*)(v + 4) = *(const float4*)(x + (size_t)i * 8 + 4);
    uint4 h, l; split8(v, h, l);
    *(uint4*)(hi + (size_t)i * 8) = h;
    *(uint4*)(lo + (size_t)i * 8) = l;
}

// ---------------------------------------------------------------------------
// Projection via bf16x3 mma.sync (round-13, unchanged).
// ---------------------------------------------------------------------------
#define PJ_TILE(b, tI) ((uint32_t)(((b) * 4 + (tI)) * 5120))
#define PJ_SMEM (8 * 5120 * 2)

__device__ __forceinline__ void proj_load_chunk(
    uint32_t sb, int b, int kt, int t, int bm, int bn)
{
    #pragma unroll
    for (int c = 0; c < 4; c++) {
        const int id = c * 512 + t;
        const int tile = id >> 9;
        const int row = (id >> 2) & 127;
        const int seg = id & 3;
        const __nv_bfloat16* p =
            (tile == 0) ? g_Xhi : (tile == 1) ? g_Xlo :
            (tile == 2) ? g_Whi : g_Wlo;
        const int rb = (tile < 2) ? bm : bn;
        const __nv_bfloat16* src = p + (size_t)(rb + row) * IND + kt + seg * 8;
        cpa16(sb + (PJ_TILE(b, tile) + (uint32_t)(row * 40 + seg * 8)) * 2, src);
    }
}

__global__ __launch_bounds__(512) void proj_mma(
    const float* __restrict__ bias, float alpha, int mode,
    float* __restrict__ dstF,
    __nv_bfloat16* __restrict__ dstHi, __nv_bfloat16* __restrict__ dstLo)
{
    extern __shared__ __align__(16) unsigned short sm[];
    const uint32_t sb = smem_u32(sm);
    const int t = threadIdx.x, lane = t & 31, w = t >> 5;
    const int wm = w >> 2, wn = w & 3;
    const int bm = blockIdx.y * 128, bn = blockIdx.x * 128;

    float acc[2][4][4];
    #pragma unroll
    for (int i = 0; i < 2; i++)
        #pragma unroll
        for (int j = 0; j < 4; j++)
            #pragma unroll
            for (int q = 0; q < 4; q++) acc[i][j][q] = 0.f;

    proj_load_chunk(sb, 0, 0, t, bm, bn);
    CP_COMMIT();

    for (int it = 0; it < 32; it++) {
        if (it + 1 < 32) {
            proj_load_chunk(sb, (it + 1) & 1, (it + 1) * 32, t, bm, bn);
            CP_COMMIT();
            CP_WAIT1();
        } else {
            CP_WAIT0();
        }
        __syncthreads();
        const int b = it & 1;
        const uint32_t ah = sb + PJ_TILE(b, 0) * 2, al = sb + PJ_TILE(b, 1) * 2;
        const uint32_t bh = sb + PJ_TILE(b, 2) * 2, bl = sb + PJ_TILE(b, 3) * 2;
        #pragma unroll
        for (int k16 = 0; k16 < 2; k16++) {
            const int k0 = k16 * 16;
            uint32_t afh[2][4], afl[2][4], bfh[2][4], bfl[2][4];
            #pragma unroll
            for (int mi = 0; mi < 2; mi++) {
                ldsm4(afh[mi], fa40(ah, wm * 32 + mi * 16, k0, lane));
                ldsm4(afl[mi], fa40(al, wm * 32 + mi * 16, k0, lane));
            }
            #pragma unroll
            for (int ng = 0; ng < 2; ng++) {
                ldsm4(bfh[ng], fa40(bh, wn * 32 + ng * 16, k0, lane));
                ldsm4(bfl[ng], fa40(bl, wn * 32 + ng * 16, k0, lane));
            }
            #pragma unroll
            for (int mi = 0; mi < 2; mi++)
                #pragma unroll
                for (int nj = 0; nj < 4; nj++) {
                    const int ng = nj >> 1, hh = nj & 1;
                    mma16816(acc[mi][nj], afh[mi], bfh[ng][hh], bfh[ng][hh + 2]);
                    mma16816(acc[mi][nj], afh[mi], bfl[ng][hh], bfl[ng][hh + 2]);
                    mma16816(acc[mi][nj], afl[mi], bfh[ng][hh], bfh[ng][hh + 2]);
                }
        }
        __syncthreads();
    }

    #pragma unroll
    for (int mi = 0; mi < 2; mi++)
        #pragma unroll
        for (int half = 0; half < 2; half++) {
            const int m = bm + wm * 32 + mi * 16 + (lane >> 2) + half * 8;
            const int bb = m >> 11, l = m & 2047;
            #pragma unroll
            for (int nj = 0; nj < 4; nj++) {
                const int c = bn + wn * 32 + nj * 8 + (lane & 3) * 2;
                const int h = c >> 6, dd = c & 63;
                const size_t idx =
                    (((size_t)(bb * NH_ + h)) * 2048 + l) * 64 + dd;
                const float v0 = alpha * (acc[mi][nj][half * 2]     + bias[c]);
                const float v1 = alpha * (acc[mi][nj][half * 2 + 1] + bias[c + 1]);
                if (mode == 0) {
                    *(float2*)&dstF[idx] = make_float2(v0, v1);
                } else {
                    __nv_bfloat16 h0 = __float2bfloat16_rn(v0);
                    __nv_bfloat16 h1 = __float2bfloat16_rn(v1);
                    __nv_bfloat16 l0 = __float2bfloat16_rn(v0 - __bfloat162float(h0));
                    __nv_bfloat16 l1 = __float2bfloat16_rn(v1 - __bfloat162float(h1));
                    *(uint32_t*)&dstHi[idx] =
                        (uint32_t)__bfloat16_as_ushort(h0) |
                        ((uint32_t)__bfloat16_as_ushort(h1) << 16);
                    *(uint32_t*)&dstLo[idx] =
                        (uint32_t)__bfloat16_as_ushort(l0) |
                        ((uint32_t)__bfloat16_as_ushort(l1) << 16);
                }
            }
        }
}

// ---------------------------------------------------------------------------
// V transpose (unchanged).
// ---------------------------------------------------------------------------
__global__ __launch_bounds__(256) void vtrans_kernel()
{
    const int z = blockIdx.y, l0 = blockIdx.x * 64;
    __shared__ float tile[64][65];
    const int t = threadIdx.x, row = t >> 2, q = t & 3;
    #pragma unroll
    for (int i = 0; i < 4; i++) {
        float4 v = *(const float4*)&g_Vf[((size_t)z * 2048 + l0 + row) * 64 + q * 16 + i * 4];
        tile[row][q * 16 + i * 4 + 0] = v.x;
        tile[row][q * 16 + i * 4 + 1] = v.y;
        tile[row][q * 16 + i * 4 + 2] = v.z;
        tile[row][q * 16 + i * 4 + 3] = v.w;
    }
    __syncthreads();
    float v[16];
    #pragma unroll
    for (int i = 0; i < 16; i++) v[i] = tile[q * 16 + i][row];
    uint4 h0, l0v, h1, l1;
    split8(v, h0, l0v); split8(v + 8, h1, l1);
    const size_t base = ((size_t)z * 64 + row) * 2048 + l0 + q * 16;
    *(uint4*)&g_Vthi[base]     = h0;  *(uint4*)&g_Vthi[base + 8] = h1;
    *(uint4*)&g_Vtlo[base]     = l0v; *(uint4*)&g_Vtlo[base + 8] = l1;
}

// ---------------------------------------------------------------------------
// QK^T via bf16x3 mma.sync. NEW epilogue: stage tile in smem (fp32, stride
// 132), then fully-coalesced mask read / stats / S write (one row-segment of
// 32 contiguous floats per thread).
// smem: max(73728 staging tiles, 128*132*4=67584) -> 73728 B.
// ---------------------------------------------------------------------------
__global__ __launch_bounds__(512) void qk_mma(
    const int* __restrict__ mask, float* __restrict__ S)
{
    extern __shared__ __align__(16) unsigned short sm[];
    const uint32_t sb = smem_u32(sm);
    const int t = threadIdx.x, lane = t & 31, w = t >> 5;
    const int wm = w >> 2, wn = w & 3;
    const int z = blockIdx.z, bm = blockIdx.y * 128, bn = blockIdx.x * 128;

    const uint32_t qh = sb, ql = sb + 9216*2, kh = sb + 18432*2, kl = sb + 27648*2;

    #pragma unroll
    for (int c = 0; c < 8; c++) {
        const int id   = c * 512 + t;
        const int tile = id >> 10;
        const int row  = (id >> 3) & 127;
        const int seg  = id & 7;
        const __nv_bfloat16* p0 =
            (tile == 0) ? g_Qhi : (tile == 1) ? g_Qlo :
            (tile == 2) ? g_Khi : g_Klo;
        const int rb = (tile < 2) ? bm : bn;
        const __nv_bfloat16* src =
            p0 + ((size_t)z * 2048 + rb + row) * 64 + seg * 8;
        const uint32_t dst = sb + (uint32_t)(tile * 9216 + row * 72 + seg * 8) * 2;
        cpa16(dst, src);
    }
    CP_COMMIT();
    CP_WAIT0();
    __syncthreads();

    float acc[2][4][4];
    #pragma unroll
    for (int i = 0; i < 2; i++)
        #pragma unroll
        for (int j = 0; j < 4; j++)
            #pragma unroll
            for (int q = 0; q < 4; q++) acc[i][j][q] = 0.f;

    #pragma unroll
    for (int k16 = 0; k16 < 4; k16++) {
        const int k0 = k16 * 16;
        uint32_t afh[2][4], afl[2][4], bfh[2][4], bfl[2][4];
        #pragma unroll
        for (int mi = 0; mi < 2; mi++) {
            ldsm4(afh[mi], fa72(qh, wm * 32 + mi * 16, k0, lane));
            ldsm4(afl[mi], fa72(ql, wm * 32 + mi * 16, k0, lane));
        }
        #pragma unroll
        for (int ng = 0; ng < 2; ng++) {
            ldsm4(bfh[ng], fa72(kh, wn * 32 + ng * 16, k0, lane));
            ldsm4(bfl[ng], fa72(kl, wn * 32 + ng * 16, k0, lane));
        }
        #pragma unroll
        for (int mi = 0; mi < 2; mi++)
            #pragma unroll
            for (int nj = 0; nj < 4; nj++) {
                const int ng = nj >> 1, hh = nj & 1;
                mma16816(acc[mi][nj], afh[mi], bfh[ng][hh], bfh[ng][hh + 2]);
                mma16816(acc[mi][nj], afh[mi], bfl[ng][hh], bfl[ng][hh + 2]);
                mma16816(acc[mi][nj], afl[mi], bfh[ng][hh], bfh[ng][hh + 2]);
            }
    }

    // stage fp32 tile to smem (MMA operand tiles are dead now)
    __syncthreads();
    float* smT = (float*)sm;   // [128][132]
    #pragma unroll
    for (int mi = 0; mi < 2; mi++)
        #pragma unroll
        for (int half = 0; half < 2; half++) {
            const int row = wm * 32 + mi * 16 + (lane >> 2) + half * 8;
            #pragma unroll
            for (int nj = 0; nj < 4; nj++) {
                const int col = wn * 32 + nj * 8 + (lane & 3) * 2;
                smT[row * 132 + col]     = acc[mi][nj][half * 2];
                smT[row * 132 + col + 1] = acc[mi][nj][half * 2 + 1];
            }
        }
    __syncthreads();

    // coalesced epilogue: thread t owns row t>>2, cols (t&3)*32 .. +31
    const int rr = t >> 2, sg = (t & 3) * 32;
    float v[32];
    #pragma unroll
    for (int j = 0; j < 32; j += 4)
        *(float4*)&v[j] = *(const float4*)&smT[rr * 132 + sg + j];
    const int* mk = mask + (size_t)(bm + rr) * LK_ + bn + sg;
    #pragma unroll
    for (int j = 0; j < 32; j += 4) {
        const int4 mm = *(const int4*)&mk[j];
        v[j]     = mm.x ? v[j]     : NEGV;
        v[j + 1] = mm.y ? v[j + 1] : NEGV;
        v[j + 2] = mm.z ? v[j + 2] : NEGV;
        v[j + 3] = mm.w ? v[j + 3] : NEGV;
    }
    float mx = v[0];
    #pragma unroll
    for (int j = 1; j < 32; j++) mx = fmaxf(mx, v[j]);
    mx = fmaxf(mx, __shfl_xor_sync(0xffffffffu, mx, 1));
    mx = fmaxf(mx, __shfl_xor_sync(0xffffffffu, mx, 2));
    float smv = 0.f;
    #pragma unroll
    for (int j = 0; j < 32; j++) smv += __expf(v[j] - mx);
    smv += __shfl_xor_sync(0xffffffffu, smv, 1);
    smv += __shfl_xor_sync(0xffffffffu, smv, 2);

    float* dst = S + (size_t)z * LQ_ * LK_ + (size_t)(bm + rr) * LK_ + bn + sg;
    #pragma unroll
    for (int j = 0; j < 32; j += 4)
        *(float4*)&dst[j] = make_float4(v[j], v[j+1], v[j+2], v[j+3]);
    if ((t & 3) == 0)
        g_part[((size_t)z * 16 + blockIdx.x) * LQ_ + bm + rr] =
            make_float2(mx, smv);
}

// ---------------------------------------------------------------------------
// Combine 16 partial stats per row -> {rowmax, 1/rowsum}.
// ---------------------------------------------------------------------------
__global__ __launch_bounds__(256) void combine_kernel()
{
    const int idx = blockIdx.x * 256 + threadIdx.x;
    if (idx >= NZ * LQ_) return;
    const int z = idx >> 11, m = idx & 2047;
    const float2* p = g_part + (size_t)z * 16 * LQ_ + m;
    float M = -3.4e38f;
    #pragma unroll
    for (int i = 0; i < 16; i++) M = fmaxf(M, p[(size_t)i * LQ_].x);
    float Ssum = 0.f;
    #pragma unroll
    for (int i = 0; i < 16; i++) {
        const float2 q = p[(size_t)i * LQ_];
        Ssum += q.y * __expf(q.x - M);
    }
    g_stats[idx] = make_float2(M, 1.0f / Ssum);
}

// ---------------------------------------------------------------------------
// PV via bf16x3 mma.sync with register S-prefetch (round-13, unchanged).
// ---------------------------------------------------------------------------
#define PV_P(b, h)  ((uint32_t)(((b) * 2 + (h)) * 5120))
#define PV_V(b, h)  ((uint32_t)(20480 + ((b) * 2 + (h)) * 2560))
#define PV_SMEM     ((20480 + 4 * 2560) * 2)

__global__ __launch_bounds__(256) void pv_mma(float* __restrict__ S)
{
    extern __shared__ __align__(16) unsigned short sm[];
    const uint32_t sb = smem_u32(sm);
    const int t = threadIdx.x, lane = t & 31, w = t >> 5;
    const int wm = w >> 1, wn = w & 1;
    const int z = blockIdx.y, bm = blockIdx.x * 128;

    const int r = t >> 1, half = t & 1;
    const float2 st = g_stats[(size_t)z * LQ_ + bm + r];
    float* Sr = S + (size_t)z * LQ_ * LK_ + (size_t)(bm + r) * LK_;

    const __nv_bfloat16* Vh0 = g_Vthi + (size_t)z * 64 * 2048;
    const __nv_bfloat16* Vl0 = g_Vtlo + (size_t)z * 64 * 2048;

    float acc[2][4][4];
    #pragma unroll
    for (int i = 0; i < 2; i++)
        #pragma unroll
        for (int j = 0; j < 4; j++)
            #pragma unroll
            for (int q = 0; q < 4; q++) acc[i][j][q] = 0.f;

    {
        #pragma unroll
        for (int c = 0; c < 2; c++) {
            const int id = c * 256 + t;
            const int hl = id >> 8;
            const int row = (id >> 2) & 63;
            const int seg = id & 3;
            const __nv_bfloat16* src =
                (hl ? Vl0 : Vh0) + (size_t)row * 2048 + 0 + seg * 8;
            cpa16(sb + (PV_V(0, hl) + (uint32_t)(row * 40 + seg * 8)) * 2, src);
        }
        CP_COMMIT();
    }
    float sreg[16];
    {
        const float* sp = Sr + half * 16;
        *(float4*)(sreg)      = *(const float4*)(sp);
        *(float4*)(sreg + 4)  = *(const float4*)(sp + 4);
        *(float4*)(sreg + 8)  = *(const float4*)(sp + 8);
        *(float4*)(sreg + 12) = *(const float4*)(sp + 12);
    }

    for (int it = 0; it < 64; it++) {
        const int kt = it * 32;
        const int pb = it & 1;
        {
            uint4 hi, lo;
            #pragma unroll
            for (int s = 0; s < 2; s++) {
                float v[8];
                #pragma unroll
                for (int j = 0; j < 8; j++)
                    v[j] = __expf(sreg[s * 8 + j] - st.x) * st.y;
                float* sp = Sr + kt + half * 16 + s * 8;
                *(float4*)(sp)     = make_float4(v[0], v[1], v[2], v[3]);
                *(float4*)(sp + 4) = make_float4(v[4], v[5], v[6], v[7]);
                split8(v, hi, lo);
                const uint32_t off = (uint32_t)(r * 40 + half * 16 + s * 8) * 2;
                *(uint4*)((char*)sm + (PV_P(pb, 0)) * 2 + off) = hi;
                *(uint4*)((char*)sm + (PV_P(pb, 1)) * 2 + off) = lo;
            }
        }
        if (it + 1 < 64) {
            const float* sp = Sr + (it + 1) * 32 + half * 16;
            *(float4*)(sreg)      = *(const float4*)(sp);
            *(float4*)(sreg + 4)  = *(const float4*)(sp + 4);
            *(float4*)(sreg + 8)  = *(const float4*)(sp + 8);
            *(float4*)(sreg + 12) = *(const float4*)(sp + 12);
        }
        if (it + 1 < 64) {
            const int vb = (it + 1) & 1;
            const int kn = (it + 1) * 32;
            #pragma unroll
            for (int c = 0; c < 2; c++) {
                const int id = c * 256 + t;
                const int hl = id >> 8;
                const int row = (id >> 2) & 63;
                const int seg = id & 3;
                const __nv_bfloat16* src =
                    (hl ? Vl0 : Vh0) + (size_t)row * 2048 + kn + seg * 8;
                cpa16(sb + (PV_V(vb, hl) + (uint32_t)(row * 40 + seg * 8)) * 2, src);
            }
            CP_COMMIT();
            CP_WAIT1();
        } else {
            CP_WAIT0();
        }
        __syncthreads();

        const uint32_t ph = sb + PV_P(pb, 0) * 2, pl = sb + PV_P(pb, 1) * 2;
        const uint32_t vh = sb + PV_V(pb, 0) * 2, vl = sb + PV_V(pb, 1) * 2;
        #pragma unroll
        for (int k16 = 0; k16 < 2; k16++) {
            const int k0 = k16 * 16;
            uint32_t afh[2][4], afl[2][4], bfh[2][4], bfl[2][4];
            #pragma unroll
            for (int mi = 0; mi < 2; mi++) {
                ldsm4(afh[mi], fa40(ph, wm * 32 + mi * 16, k0, lane));
                ldsm4(afl[mi], fa40(pl, wm * 32 + mi * 16, k0, lane));
            }
            #pragma unroll
            for (int ng = 0; ng < 2; ng++) {
                ldsm4(bfh[ng], fa40(vh, wn * 32 + ng * 16, k0, lane));
                ldsm4(bfl[ng], fa40(vl, wn * 32 + ng * 16, k0, lane));
            }
            #pragma unroll
            for (int mi = 0; mi < 2; mi++)
                #pragma unroll
                for (int nj = 0; nj < 4; nj++) {
                    const int ng = nj >> 1, hh = nj & 1;
                    mma16816(acc[mi][nj], afh[mi], bfh[ng][hh], bfh[ng][hh + 2]);
                    mma16816(acc[mi][nj], afh[mi], bfl[ng][hh], bfl[ng][hh + 2]);
                    mma16816(acc[mi][nj], afl[mi], bfh[ng][hh], bfh[ng][hh + 2]);
                }
        }
        __syncthreads();
    }

    const int bb = z >> 4, h = z & 15;
    #pragma unroll
    for (int mi = 0; mi < 2; mi++)
        #pragma unroll
        for (int nj = 0; nj < 4; nj++) {
            const int r0 = bm + wm * 32 + mi * 16 + (lane >> 2);
            const int c  = wn * 32 + nj * 8 + (lane & 3) * 2;
            #pragma unroll
            for (int hf = 0; hf < 2; hf++) {
                const int rr = r0 + hf * 8;
                *(float2*)&g_Oh[((size_t)bb * LQ_ + rr) * HDA + h * 64 + c] =
                    make_float2(acc[mi][nj][hf * 2], acc[mi][nj][hf * 2 + 1]);
            }
        }
}

// ---------------------------------------------------------------------------
// Output GEMM with 4-way K split + atomics. out pre-initialized with bias.
// ---------------------------------------------------------------------------
__global__ __launch_bounds__(256) void o_init(
    const float* __restrict__ bo, float* __restrict__ out)
{
    const int i = blockIdx.x * 256 + threadIdx.x;   // over 8192*64/2
    const int n = (i * 2) & 63;
    *(float2*)&out[(size_t)i * 2] = make_float2(bo[n], bo[n + 1]);
}

__global__ __launch_bounds__(256) void o_split(
    const float* __restrict__ wo, float* __restrict__ out)
{
    const int bm = blockIdx.x * 64;
    const int ks = blockIdx.y * 256;
    __shared__ float As[16][68];
    __shared__ float Ws[16][68];
    const int t  = threadIdx.x;
    const int tx = t % 16, ty = t / 16;
    const int lk = t % 16, lr = t / 16;

    u64 acc2[4][2];
    #pragma unroll
    for (int i = 0; i < 4; i++) {
        acc2[i][0] = pack2(0.f, 0.f);
        acc2[i][1] = pack2(0.f, 0.f);
    }

    for (int kt = ks; kt < ks + 256; kt += 16) {
        #pragma unroll
        for (int i = 0; i < 4; i++) {
            const int m = i * 16 + lr;
            As[lk][m] = g_Oh[(size_t)(bm + m) * HDA + kt + lk];
            Ws[lk][m] = wo  [(size_t)m        * HDA + kt + lk];
        }
        __syncthreads();
        #pragma unroll
        for (int kk = 0; kk < 16; kk++) {
            float a[4], b[4];
            #pragma unroll
            for (int i = 0; i < 4; i++) a[i] = As[kk][ty * 4 + i];
            #pragma unroll
            for (int j = 0; j < 4; j++) b[j] = Ws[kk][tx + 16 * j];
            const u64 b20 = pack2(b[0], b[1]);
            const u64 b21 = pack2(b[2], b[3]);
            #pragma unroll
            for (int i = 0; i < 4; i++) {
                const u64 a2 = pack2(a[i], a[i]);
                acc2[i][0] = ffma2(a2, b20, acc2[i][0]);
                acc2[i][1] = ffma2(a2, b21, acc2[i][1]);
            }
        }
        __syncthreads();
    }

    #pragma unroll
    for (int i = 0; i < 4; i++) {
        const int m = bm + ty * 4 + i;
        float2 p0 = unpack2(acc2[i][0]), p1 = unpack2(acc2[i][1]);
        atomicAdd(&out[(size_t)m * HD_ + tx],      p0.x);
        atomicAdd(&out[(size_t)m * HD_ + tx + 16], p0.y);
        atomicAdd(&out[(size_t)m * HD_ + tx + 32], p1.x);
        atomicAdd(&out[(size_t)m * HD_ + tx + 48], p1.y);
    }
}

// ---------------------------------------------------------------------------
extern "C" void kernel_launch(void* const* d_in, const int* in_sizes, int n_in,
                              void* d_out, int out_size)
{
    (void)in_sizes; (void)n_in; (void)out_size;
    const float* q    = (const float*)d_in[0];
    const float* k    = (const float*)d_in[1];
    const float* v    = (const float*)d_in[2];
    const int*   mask = (const int*)  d_in[3];
    const float* wq   = (const float*)d_in[4];
    const float* bq   = (const float*)d_in[5];
    const float* wk   = (const float*)d_in[6];
    const float* bk   = (const float*)d_in[7];
    const float* wv   = (const float*)d_in[8];
    const float* bv   = (const float*)d_in[9];
    const float* wo   = (const float*)d_in[10];
    const float* bo   = (const float*)d_in[11];

    float* out    = (float*)d_out;                       // [B, LQ, 64]
    float* scores = out + (size_t)B_ * LQ_ * HD_;        // [B, H, LQ, LK]

    __nv_bfloat16 *Xhi, *Xlo, *Whi, *Wlo, *Qhi, *Qlo, *Khi, *Klo;
    float* Vf;
    cudaGetSymbolAddress((void**)&Xhi, g_Xhi);
    cudaGetSymbolAddress((void**)&Xlo, g_Xlo);
    cudaGetSymbolAddress((void**)&Whi, g_Whi);
    cudaGetSymbolAddress((void**)&Wlo, g_Wlo);
    cudaGetSymbolAddress((void**)&Qhi, g_Qhi);
    cudaGetSymbolAddress((void**)&Qlo, g_Qlo);
    cudaGetSymbolAddress((void**)&Khi, g_Khi);
    cudaGetSymbolAddress((void**)&Klo, g_Klo);
    cudaGetSymbolAddress((void**)&Vf,  g_Vf);

    const int QK_SMEM = 4 * 128 * 72 * 2;                // 73728 B
    cudaFuncSetAttribute(qk_mma, cudaFuncAttributeMaxDynamicSharedMemorySize,
                         QK_SMEM);
    cudaFuncSetAttribute(pv_mma, cudaFuncAttributeMaxDynamicSharedMemorySize,
                         PV_SMEM);
    cudaFuncSetAttribute(proj_mma, cudaFuncAttributeMaxDynamicSharedMemorySize,
                         PJ_SMEM);

    const dim3 blk(256);
    const int  NX8 = (B_ * LQ_ * IND) / 8;
    const int  NW8 = (IND * IND) / 8;
    const dim3 gproj(IND / 128, (B_ * LQ_) / 128);       // (8, 64)

    split_kernel<<<NX8 / 256, blk>>>(q, Xhi, Xlo, NX8);
    split_kernel<<<NW8 / 256, blk>>>(wq, Whi, Wlo, NW8);
    proj_mma<<<gproj, 512, PJ_SMEM>>>(bq, 0.125f, 1, nullptr, Qhi, Qlo);
    split_kernel<<<NX8 / 256, blk>>>(k, Xhi, Xlo, NX8);
    split_kernel<<<NW8 / 256, blk>>>(wk, Whi, Wlo, NW8);
    proj_mma<<<gproj, 512, PJ_SMEM>>>(bk, 1.0f, 1, nullptr, Khi, Klo);
    split_kernel<<<NX8 / 256, blk>>>(v, Xhi, Xlo, NX8);
    split_kernel<<<NW8 / 256, blk>>>(wv, Whi, Wlo, NW8);
    proj_mma<<<gproj, 512, PJ_SMEM>>>(bv, 1.0f, 0, Vf, nullptr, nullptr);

    vtrans_kernel<<<dim3(LK_ / 64, NZ), blk>>>();        // (32, 64)

    qk_mma<<<dim3(LK_ / 128, LQ_ / 128, NZ), 512, QK_SMEM>>>(mask, scores);

    combine_kernel<<<(NZ * LQ_ + 255) / 256, blk>>>();   // 512 blocks

    pv_mma<<<dim3(LQ_ / 128, NZ), blk, PV_SMEM>>>(scores);

    o_init<<<(B_ * LQ_ * HD_ / 2) / 256, blk>>>(bo, out);   // 1024 blocks
    o_split<<<dim3((B_ * LQ_) / 64, 4), blk>>>(wo, out);    // (128, 4)
}

// round 15
// speedup vs baseline: 1.0628x; 1.0628x over previous
#include <cuda_runtime.h>
#include <cuda_bf16.h>
#include <math.h>
#include <cstdint>

#define B_   4
#define LQ_  2048
#define LK_  2048
#define IND  1024
#define NH_  16
#define HD_  64
#define HDA  1024
#define NZ   (B_*NH_)
#define NEGV (-1e9f)

typedef unsigned long long u64;

// Scratch (device globals)
__device__ __nv_bfloat16 g_Xhi[(size_t)B_ * LQ_ * IND];
__device__ __nv_bfloat16 g_Xlo[(size_t)B_ * LQ_ * IND];
__device__ __nv_bfloat16 g_Whi[(size_t)IND * IND];
__device__ __nv_bfloat16 g_Wlo[(size_t)IND * IND];
__device__ __nv_bfloat16 g_Qhi[(size_t)NZ * LQ_ * HD_];
__device__ __nv_bfloat16 g_Qlo[(size_t)NZ * LQ_ * HD_];
__device__ __nv_bfloat16 g_Khi[(size_t)NZ * LK_ * HD_];
__device__ __nv_bfloat16 g_Klo[(size_t)NZ * LK_ * HD_];
__device__ __nv_bfloat16 g_Vthi[(size_t)NZ * HD_ * LK_];
__device__ __nv_bfloat16 g_Vtlo[(size_t)NZ * HD_ * LK_];
__device__ float  g_Vf[(size_t)NZ * LK_ * HD_];
__device__ float  g_Oh[(size_t)B_ * LQ_ * HDA];
__device__ float2 g_part[(size_t)NZ * 64 * LQ_];
__device__ float2 g_stats[(size_t)NZ * LQ_];

// ---------------- helpers ----------------
__device__ __forceinline__ u64 pack2(float x, float y) {
    u64 r; asm("mov.b64 %0, {%1, %2};" : "=l"(r) : "f"(x), "f"(y)); return r;
}
__device__ __forceinline__ float2 unpack2(u64 v) {
    float x, y; asm("mov.b64 {%0, %1}, %2;" : "=f"(x), "=f"(y) : "l"(v));
    return make_float2(x, y);
}
__device__ __forceinline__ u64 ffma2(u64 a, u64 b, u64 c) {
    u64 d; asm("fma.rn.f32x2 %0, %1, %2, %3;" : "=l"(d) : "l"(a), "l"(b), "l"(c));
    return d;
}
__device__ __forceinline__ uint32_t smem_u32(const void* p) {
    uint32_t a;
    asm("{ .reg .u64 t; cvta.to.shared.u64 t, %1; cvt.u32.u64 %0, t; }" : "=r"(a) : "l"(p));
    return a;
}
__device__ __forceinline__ void cpa16(uint32_t dst, const void* src) {
    asm volatile("cp.async.cg.shared.global [%0], [%1], 16;" :: "r"(dst), "l"(src));
}
#define CP_COMMIT() asm volatile("cp.async.commit_group;" ::: "memory")
#define CP_WAIT0()  asm volatile("cp.async.wait_group 0;" ::: "memory")
#define CP_WAIT1()  asm volatile("cp.async.wait_group 1;" ::: "memory")

__device__ __forceinline__ void ldsm4(uint32_t (&r)[4], uint32_t addr) {
    asm volatile("ldmatrix.sync.aligned.m8n8.x4.shared.b16 {%0,%1,%2,%3}, [%4];"
                 : "=r"(r[0]), "=r"(r[1]), "=r"(r[2]), "=r"(r[3]) : "r"(addr));
}
__device__ __forceinline__ uint32_t fa72(uint32_t base, int row0, int k0, int lane) {
    const int g = lane >> 3;
    const int row = row0 + (lane & 7) + ((g & 1) << 3);
    const int col = k0 + ((g >> 1) << 3);
    return base + (uint32_t)(row * 72 + col) * 2;
}
__device__ __forceinline__ uint32_t fa40(uint32_t base, int row0, int k0, int lane) {
    const int g = lane >> 3;
    const int row = row0 + (lane & 7) + ((g & 1) << 3);
    const int col = k0 + ((g >> 1) << 3);
    return base + (uint32_t)(row * 40 + col) * 2;
}
__device__ __forceinline__ void mma16816(float (&d)[4], const uint32_t (&a)[4],
                                         uint32_t b0, uint32_t b1) {
    asm volatile(
        "mma.sync.aligned.m16n8k16.row.col.f32.bf16.bf16.f32 "
        "{%0,%1,%2,%3},{%4,%5,%6,%7},{%8,%9},{%0,%1,%2,%3};"
        : "+f"(d[0]), "+f"(d[1]), "+f"(d[2]), "+f"(d[3])
        : "r"(a[0]), "r"(a[1]), "r"(a[2]), "r"(a[3]), "r"(b0), "r"(b1));
}
__device__ __forceinline__ void split8(const float* v, uint4& hi, uint4& lo) {
    unsigned short h[8], l[8];
    #pragma unroll
    for (int i = 0; i < 8; i++) {
        __nv_bfloat16 hb = __float2bfloat16_rn(v[i]);
        __nv_bfloat16 lb = __float2bfloat16_rn(v[i] - __bfloat162float(hb));
        h[i] = __bfloat16_as_ushort(hb);
        l[i] = __bfloat16_as_ushort(lb);
    }
    hi.x = h[0] | ((uint32_t)h[1] << 16); hi.y = h[2] | ((uint32_t)h[3] << 16);
    hi.z = h[4] | ((uint32_t)h[5] << 16); hi.w = h[6] | ((uint32_t)h[7] << 16);
    lo.x = l[0] | ((uint32_t)l[1] << 16); lo.y = l[2] | ((uint32_t)l[3] << 16);
    lo.z = l[4] | ((uint32_t)l[5] << 16); lo.w = l[6] | ((uint32_t)l[7] << 16);
}
__device__ __forceinline__ uint32_t splitbf2(float v0, float v1, uint32_t& lo) {
    __nv_bfloat16 h0 = __float2bfloat16_rn(v0);
    __nv_bfloat16 h1 = __float2bfloat16_rn(v1);
    __nv_bfloat16 l0 = __float2bfloat16_rn(v0 - __bfloat162float(h0));
    __nv_bfloat16 l1 = __float2bfloat16_rn(v1 - __bfloat162float(h1));
    lo = (uint32_t)__bfloat16_as_ushort(l0) | ((uint32_t)__bfloat16_as_ushort(l1) << 16);
    return (uint32_t)__bfloat16_as_ushort(h0) | ((uint32_t)__bfloat16_as_ushort(h1) << 16);
}

// ---------------------------------------------------------------------------
// Split fp32 -> bf16 hi/lo (streaming).
// ---------------------------------------------------------------------------
__global__ __launch_bounds__(256) void split_kernel(
    const float* __restrict__ x, __nv_bfloat16* __restrict__ hi,
    __nv_bfloat16* __restrict__ lo, int n8)
{
    const int i = blockIdx.x * 256 + threadIdx.x;
    if (i >= n8) return;
    float v[8];
    *(float4*)v       = *(const float4*)(x + (size_t)i * 8);
    *(float4*)(v + 4) = *(const float4*)(x + (size_t)i * 8 + 4);
    uint4 h, l; split8(v, h, l);
    *(uint4*)(hi + (size_t)i * 8) = h;
    *(uint4*)(lo + (size_t)i * 8) = l;
}

// ---------------------------------------------------------------------------
// Projection via bf16x3 mma.sync (round-13, unchanged).
// ---------------------------------------------------------------------------
#define PJ_TILE(b, tI) ((uint32_t)(((b) * 4 + (tI)) * 5120))
#define PJ_SMEM (8 * 5120 * 2)

__device__ __forceinline__ void proj_load_chunk(
    uint32_t sb, int b, int kt, int t, int bm, int bn)
{
    #pragma unroll
    for (int c = 0; c < 4; c++) {
        const int id = c * 512 + t;
        const int tile = id >> 9;
        const int row = (id >> 2) & 127;
        const int seg = id & 3;
        const __nv_bfloat16* p =
            (tile == 0) ? g_Xhi : (tile == 1) ? g_Xlo :
            (tile == 2) ? g_Whi : g_Wlo;
        const int rb = (tile < 2) ? bm : bn;
        const __nv_bfloat16* src = p + (size_t)(rb + row) * IND + kt + seg * 8;
        cpa16(sb + (PJ_TILE(b, tile) + (uint32_t)(row * 40 + seg * 8)) * 2, src);
    }
}

__global__ __launch_bounds__(512) void proj_mma(
    const float* __restrict__ bias, float alpha, int mode,
    float* __restrict__ dstF,
    __nv_bfloat16* __restrict__ dstHi, __nv_bfloat16* __restrict__ dstLo)
{
    extern __shared__ __align__(16) unsigned short sm[];
    const uint32_t sb = smem_u32(sm);
    const int t = threadIdx.x, lane = t & 31, w = t >> 5;
    const int wm = w >> 2, wn = w & 3;
    const int bm = blockIdx.y * 128, bn = blockIdx.x * 128;

    float acc[2][4][4];
    #pragma unroll
    for (int i = 0; i < 2; i++)
        #pragma unroll
        for (int j = 0; j < 4; j++)
            #pragma unroll
            for (int q = 0; q < 4; q++) acc[i][j][q] = 0.f;

    proj_load_chunk(sb, 0, 0, t, bm, bn);
    CP_COMMIT();

    for (int it = 0; it < 32; it++) {
        if (it + 1 < 32) {
            proj_load_chunk(sb, (it + 1) & 1, (it + 1) * 32, t, bm, bn);
            CP_COMMIT();
            CP_WAIT1();
        } else {
            CP_WAIT0();
        }
        __syncthreads();
        const int b = it & 1;
        const uint32_t ah = sb + PJ_TILE(b, 0) * 2, al = sb + PJ_TILE(b, 1) * 2;
        const uint32_t bh = sb + PJ_TILE(b, 2) * 2, bl = sb + PJ_TILE(b, 3) * 2;
        #pragma unroll
        for (int k16 = 0; k16 < 2; k16++) {
            const int k0 = k16 * 16;
            uint32_t afh[2][4], afl[2][4], bfh[2][4], bfl[2][4];
            #pragma unroll
            for (int mi = 0; mi < 2; mi++) {
                ldsm4(afh[mi], fa40(ah, wm * 32 + mi * 16, k0, lane));
                ldsm4(afl[mi], fa40(al, wm * 32 + mi * 16, k0, lane));
            }
            #pragma unroll
            for (int ng = 0; ng < 2; ng++) {
                ldsm4(bfh[ng], fa40(bh, wn * 32 + ng * 16, k0, lane));
                ldsm4(bfl[ng], fa40(bl, wn * 32 + ng * 16, k0, lane));
            }
            #pragma unroll
            for (int mi = 0; mi < 2; mi++)
                #pragma unroll
                for (int nj = 0; nj < 4; nj++) {
                    const int ng = nj >> 1, hh = nj & 1;
                    mma16816(acc[mi][nj], afh[mi], bfh[ng][hh], bfh[ng][hh + 2]);
                    mma16816(acc[mi][nj], afh[mi], bfl[ng][hh], bfl[ng][hh + 2]);
                    mma16816(acc[mi][nj], afl[mi], bfh[ng][hh], bfh[ng][hh + 2]);
                }
        }
        __syncthreads();
    }

    #pragma unroll
    for (int mi = 0; mi < 2; mi++)
        #pragma unroll
        for (int half = 0; half < 2; half++) {
            const int m = bm + wm * 32 + mi * 16 + (lane >> 2) + half * 8;
            const int bb = m >> 11, l = m & 2047;
            #pragma unroll
            for (int nj = 0; nj < 4; nj++) {
                const int c = bn + wn * 32 + nj * 8 + (lane & 3) * 2;
                const int h = c >> 6, dd = c & 63;
                const size_t idx =
                    (((size_t)(bb * NH_ + h)) * 2048 + l) * 64 + dd;
                const float v0 = alpha * (acc[mi][nj][half * 2]     + bias[c]);
                const float v1 = alpha * (acc[mi][nj][half * 2 + 1] + bias[c + 1]);
                if (mode == 0) {
                    *(float2*)&dstF[idx] = make_float2(v0, v1);
                } else {
                    uint32_t lo;
                    const uint32_t hi = splitbf2(v0, v1, lo);
                    *(uint32_t*)&dstHi[idx] = hi;
                    *(uint32_t*)&dstLo[idx] = lo;
                }
            }
        }
}

// ---------------------------------------------------------------------------
// V transpose (unchanged).
// ---------------------------------------------------------------------------
__global__ __launch_bounds__(256) void vtrans_kernel()
{
    const int z = blockIdx.y, l0 = blockIdx.x * 64;
    __shared__ float tile[64][65];
    const int t = threadIdx.x, row = t >> 2, q = t & 3;
    #pragma unroll
    for (int i = 0; i < 4; i++) {
        float4 v = *(const float4*)&g_Vf[((size_t)z * 2048 + l0 + row) * 64 + q * 16 + i * 4];
        tile[row][q * 16 + i * 4 + 0] = v.x;
        tile[row][q * 16 + i * 4 + 1] = v.y;
        tile[row][q * 16 + i * 4 + 2] = v.z;
        tile[row][q * 16 + i * 4 + 3] = v.w;
    }
    __syncthreads();
    float v[16];
    #pragma unroll
    for (int i = 0; i < 16; i++) v[i] = tile[q * 16 + i][row];
    uint4 h0, l0v, h1, l1;
    split8(v, h0, l0v); split8(v + 8, h1, l1);
    const size_t base = ((size_t)z * 64 + row) * 2048 + l0 + q * 16;
    *(uint4*)&g_Vthi[base]     = h0;  *(uint4*)&g_Vthi[base + 8] = h1;
    *(uint4*)&g_Vtlo[base]     = l0v; *(uint4*)&g_Vtlo[base + 8] = l1;
}

// ---------------------------------------------------------------------------
// Pass 1: QK^T stats only (round-10 qk minus S stores).
// ---------------------------------------------------------------------------
__global__ __launch_bounds__(512) void qk_stats(const int* __restrict__ mask)
{
    extern __shared__ __align__(16) unsigned short sm[];
    const uint32_t sb = smem_u32(sm);
    const int t = threadIdx.x, lane = t & 31, w = t >> 5;
    const int wm = w >> 2, wn = w & 3;
    const int z = blockIdx.z, bm = blockIdx.y * 128, bn = blockIdx.x * 128;

    const uint32_t qh = sb, ql = sb + 9216*2, kh = sb + 18432*2, kl = sb + 27648*2;

    #pragma unroll
    for (int c = 0; c < 8; c++) {
        const int id   = c * 512 + t;
        const int tile = id >> 10;
        const int row  = (id >> 3) & 127;
        const int seg  = id & 7;
        const __nv_bfloat16* p0 =
            (tile == 0) ? g_Qhi : (tile == 1) ? g_Qlo :
            (tile == 2) ? g_Khi : g_Klo;
        const int rb = (tile < 2) ? bm : bn;
        const __nv_bfloat16* src =
            p0 + ((size_t)z * 2048 + rb + row) * 64 + seg * 8;
        const uint32_t dst = sb + (uint32_t)(tile * 9216 + row * 72 + seg * 8) * 2;
        cpa16(dst, src);
    }
    CP_COMMIT();
    CP_WAIT0();
    __syncthreads();

    float acc[2][4][4];
    #pragma unroll
    for (int i = 0; i < 2; i++)
        #pragma unroll
        for (int j = 0; j < 4; j++)
            #pragma unroll
            for (int q = 0; q < 4; q++) acc[i][j][q] = 0.f;

    #pragma unroll
    for (int k16 = 0; k16 < 4; k16++) {
        const int k0 = k16 * 16;
        uint32_t afh[2][4], afl[2][4], bfh[2][4], bfl[2][4];
        #pragma unroll
        for (int mi = 0; mi < 2; mi++) {
            ldsm4(afh[mi], fa72(qh, wm * 32 + mi * 16, k0, lane));
            ldsm4(afl[mi], fa72(ql, wm * 32 + mi * 16, k0, lane));
        }
        #pragma unroll
        for (int ng = 0; ng < 2; ng++) {
            ldsm4(bfh[ng], fa72(kh, wn * 32 + ng * 16, k0, lane));
            ldsm4(bfl[ng], fa72(kl, wn * 32 + ng * 16, k0, lane));
        }
        #pragma unroll
        for (int mi = 0; mi < 2; mi++)
            #pragma unroll
            for (int nj = 0; nj < 4; nj++) {
                const int ng = nj >> 1, hh = nj & 1;
                mma16816(acc[mi][nj], afh[mi], bfh[ng][hh], bfh[ng][hh + 2]);
                mma16816(acc[mi][nj], afh[mi], bfl[ng][hh], bfl[ng][hh + 2]);
                mma16816(acc[mi][nj], afl[mi], bfh[ng][hh], bfh[ng][hh + 2]);
            }
    }

    float2* part = g_part + ((size_t)z * 64 + blockIdx.x * 4 + wn) * LQ_;
    #pragma unroll
    for (int mi = 0; mi < 2; mi++)
        #pragma unroll
        for (int half = 0; half < 2; half++) {
            const int r = bm + wm * 32 + mi * 16 + (lane >> 2) + half * 8;
            float v[8];
            #pragma unroll
            for (int nj = 0; nj < 4; nj++) {
                const int c = bn + wn * 32 + nj * 8 + (lane & 3) * 2;
                const int2 mm = *(const int2*)&mask[(size_t)r * LK_ + c];
                v[nj * 2]     = mm.x ? acc[mi][nj][half * 2]     : NEGV;
                v[nj * 2 + 1] = mm.y ? acc[mi][nj][half * 2 + 1] : NEGV;
            }
            float mx = v[0];
            #pragma unroll
            for (int j = 1; j < 8; j++) mx = fmaxf(mx, v[j]);
            mx = fmaxf(mx, __shfl_xor_sync(0xffffffffu, mx, 1));
            mx = fmaxf(mx, __shfl_xor_sync(0xffffffffu, mx, 2));
            float smv = 0.f;
            #pragma unroll
            for (int j = 0; j < 8; j++) smv += __expf(v[j] - mx);
            smv += __shfl_xor_sync(0xffffffffu, smv, 1);
            smv += __shfl_xor_sync(0xffffffffu, smv, 2);
            if ((lane & 3) == 0) part[r] = make_float2(mx, smv);
        }
}

// ---------------------------------------------------------------------------
// Combine 64 partial stats per row -> {rowmax, 1/rowsum}.
// ---------------------------------------------------------------------------
__global__ __launch_bounds__(256) void combine_kernel()
{
    const int idx = blockIdx.x * 256 + threadIdx.x;
    if (idx >= NZ * LQ_) return;
    const int z = idx >> 11, m = idx & 2047;
    const float2* p = g_part + (size_t)z * 64 * LQ_ + m;
    float M = -3.4e38f;
    #pragma unroll 8
    for (int i = 0; i < 64; i++) M = fmaxf(M, p[(size_t)i * LQ_].x);
    float Ssum = 0.f;
    #pragma unroll 8
    for (int i = 0; i < 64; i++) {
        const float2 q = p[(size_t)i * LQ_];
        Ssum += q.y * __expf(q.x - M);
    }
    g_stats[idx] = make_float2(M, 1.0f / Ssum);
}

// ---------------------------------------------------------------------------
// Pass 2 (fused): recompute QK^T, mask+exp-normalize, write final S once,
// chain into PV. CTA = 128 q-rows x full K loop (64-token chunks, dbuf).
// 512 threads = 16 warps (4m x 4n); warp tiles: S 32x16, O 32x16.
// smem halves: Q(hi,lo)[128][72]; K(hi,lo)x2[64][72]; V(hi,lo)x2[64][72];
//              P(hi,lo)[128][72]  -> 73728 halves = 147456 B.
// ---------------------------------------------------------------------------
#define A_QH 0
#define A_QL 9216
#define A_KH(b) (18432 + (b) * 9216)
#define A_KL(b) (23040 + (b) * 9216)
#define A_VH(b) (36864 + (b) * 9216)
#define A_VL(b) (41472 + (b) * 9216)
#define A_PH 55296
#define A_PL 64512
#define ATTN_SMEM (73728 * 2)

__device__ __forceinline__ void attn_load_kv(
    uint32_t sb, int b, int kt, int t, int z)
{
    #pragma unroll
    for (int c = 0; c < 4; c++) {
        const int id = c * 512 + t;
        const int part = id >> 10;            // 0 = K, 1 = V
        const int arr = (id >> 9) & 1;        // 0 = hi, 1 = lo
        const int row = (id >> 3) & 63;
        const int seg = id & 7;
        if (part == 0) {
            const __nv_bfloat16* src =
                (arr ? g_Klo : g_Khi) + ((size_t)z * 2048 + kt + row) * 64 + seg * 8;
            cpa16(sb + (uint32_t)((arr ? A_KL(b) : A_KH(b)) + row * 72 + seg * 8) * 2, src);
        } else {
            const __nv_bfloat16* src =
                (arr ? g_Vtlo : g_Vthi) + ((size_t)z * 64 + row) * 2048 + kt + seg * 8;
            cpa16(sb + (uint32_t)((arr ? A_VL(b) : A_VH(b)) + row * 72 + seg * 8) * 2, src);
        }
    }
}

__global__ __launch_bounds__(512) void attn_mma(
    const int* __restrict__ mask, float* __restrict__ S)
{
    extern __shared__ __align__(16) unsigned short sm[];
    const uint32_t sb = smem_u32(sm);
    const int t = threadIdx.x, lane = t & 31, w = t >> 5;
    const int wm = w >> 2, wn = w & 3;
    const int z = blockIdx.y, bm = blockIdx.x * 128;

    // prologue: load Q tile + KV chunk 0
    #pragma unroll
    for (int c = 0; c < 4; c++) {
        const int id = c * 512 + t;
        const int arr = id >> 10;
        const int row = (id >> 3) & 127;
        const int seg = id & 7;
        const __nv_bfloat16* src =
            (arr ? g_Qlo : g_Qhi) + ((size_t)z * 2048 + bm + row) * 64 + seg * 8;
        cpa16(sb + (uint32_t)((arr ? A_QL : A_QH) + row * 72 + seg * 8) * 2, src);
    }
    attn_load_kv(sb, 0, 0, t, z);
    CP_COMMIT();

    // per-thread stats for the 4 rows this thread's fragments touch
    const int r0 = wm * 32 + (lane >> 2);
    float2 st[4];
    #pragma unroll
    for (int mi = 0; mi < 2; mi++)
        #pragma unroll
        for (int hf = 0; hf < 2; hf++)
            st[mi * 2 + hf] = g_stats[(size_t)z * LQ_ + bm + r0 + mi * 16 + hf * 8];

    float accO[2][2][4];
    #pragma unroll
    for (int i = 0; i < 2; i++)
        #pragma unroll
        for (int j = 0; j < 2; j++)
            #pragma unroll
            for (int q = 0; q < 4; q++) accO[i][j][q] = 0.f;

    for (int it = 0; it < 32; it++) {
        const int kt = it * 64;
        const int b = it & 1;
        CP_WAIT0();
        __syncthreads();                     // chunk it ready; P free (MMA2 it-1 done)
        if (it + 1 < 32) {
            attn_load_kv(sb, (it + 1) & 1, kt + 64, t, z);
            CP_COMMIT();
        }

        // MMA1: S tile [128 x 64] = Q . K^T (bf16x3)
        float accS[2][2][4];
        #pragma unroll
        for (int i = 0; i < 2; i++)
            #pragma unroll
            for (int j = 0; j < 2; j++)
                #pragma unroll
                for (int q = 0; q < 4; q++) accS[i][j][q] = 0.f;
        #pragma unroll
        for (int k16 = 0; k16 < 4; k16++) {
            const int k0 = k16 * 16;
            uint32_t afh[2][4], afl[2][4], bfh[4], bfl[4];
            #pragma unroll
            for (int mi = 0; mi < 2; mi++) {
                ldsm4(afh[mi], fa72(sb + A_QH * 2, wm * 32 + mi * 16, k0, lane));
                ldsm4(afl[mi], fa72(sb + A_QL * 2, wm * 32 + mi * 16, k0, lane));
            }
            ldsm4(bfh, fa72(sb + A_KH(b) * 2, wn * 16, k0, lane));
            ldsm4(bfl, fa72(sb + A_KL(b) * 2, wn * 16, k0, lane));
            #pragma unroll
            for (int mi = 0; mi < 2; mi++)
                #pragma unroll
                for (int nj = 0; nj < 2; nj++) {
                    mma16816(accS[mi][nj], afh[mi], bfh[nj], bfh[nj + 2]);
                    mma16816(accS[mi][nj], afh[mi], bfl[nj], bfl[nj + 2]);
                    mma16816(accS[mi][nj], afl[mi], bfh[nj], bfh[nj + 2]);
                }
        }

        // mask + exp-normalize; write final S; stage P to smem
        #pragma unroll
        for (int mi = 0; mi < 2; mi++)
            #pragma unroll
            for (int hf = 0; hf < 2; hf++) {
                const int row = wm * 32 + mi * 16 + (lane >> 2) + hf * 8;
                const float2 s2 = st[mi * 2 + hf];
                #pragma unroll
                for (int nj = 0; nj < 2; nj++) {
                    const int col = wn * 16 + nj * 8 + (lane & 3) * 2;
                    const int2 mm = *(const int2*)&mask[(size_t)(bm + row) * LK_ + kt + col];
                    float v0 = mm.x ? accS[mi][nj][hf * 2]     : NEGV;
                    float v1 = mm.y ? accS[mi][nj][hf * 2 + 1] : NEGV;
                    v0 = __expf(v0 - s2.x) * s2.y;
                    v1 = __expf(v1 - s2.x) * s2.y;
                    *(float2*)&S[(size_t)z * LQ_ * LK_ +
                                 (size_t)(bm + row) * LK_ + kt + col] =
                        make_float2(v0, v1);
                    uint32_t lo;
                    const uint32_t hi = splitbf2(v0, v1, lo);
                    *(uint32_t*)((char*)sm + (uint32_t)(A_PH + row * 72 + col) * 2) = hi;
                    *(uint32_t*)((char*)sm + (uint32_t)(A_PL + row * 72 + col) * 2) = lo;
                }
            }
        __syncthreads();                     // P visible

        // MMA2: O += P . V  (k = 64 tokens)
        #pragma unroll
        for (int k16 = 0; k16 < 4; k16++) {
            const int k0 = k16 * 16;
            uint32_t afh[2][4], afl[2][4], bfh[4], bfl[4];
            #pragma unroll
            for (int mi = 0; mi < 2; mi++) {
                ldsm4(afh[mi], fa72(sb + A_PH * 2, wm * 32 + mi * 16, k0, lane));
                ldsm4(afl[mi], fa72(sb + A_PL * 2, wm * 32 + mi * 16, k0, lane));
            }
            ldsm4(bfh, fa72(sb + A_VH(b) * 2, wn * 16, k0, lane));
            ldsm4(bfl, fa72(sb + A_VL(b) * 2, wn * 16, k0, lane));
            #pragma unroll
            for (int mi = 0; mi < 2; mi++)
                #pragma unroll
                for (int nj = 0; nj < 2; nj++) {
                    mma16816(accO[mi][nj], afh[mi], bfh[nj], bfh[nj + 2]);
                    mma16816(accO[mi][nj], afh[mi], bfl[nj], bfl[nj + 2]);
                    mma16816(accO[mi][nj], afl[mi], bfh[nj], bfh[nj + 2]);
                }
        }
    }

    // epilogue: O tile -> g_Oh
    const int bb = z >> 4, h = z & 15;
    #pragma unroll
    for (int mi = 0; mi < 2; mi++)
        #pragma unroll
        for (int nj = 0; nj < 2; nj++) {
            const int rr0 = bm + wm * 32 + mi * 16 + (lane >> 2);
            const int c   = wn * 16 + nj * 8 + (lane & 3) * 2;
            #pragma unroll
            for (int hf = 0; hf < 2; hf++) {
                const int rr = rr0 + hf * 8;
                *(float2*)&g_Oh[((size_t)bb * LQ_ + rr) * HDA + h * 64 + c] =
                    make_float2(accO[mi][nj][hf * 2], accO[mi][nj][hf * 2 + 1]);
            }
        }
}

// ---------------------------------------------------------------------------
// Output GEMM (round-13): out = Oh @ wo^T + bo.
// ---------------------------------------------------------------------------
__global__ __launch_bounds__(256) void o_kernel(
    const float* __restrict__ wo, const float* __restrict__ bo,
    float* __restrict__ out)
{
    const int bm = blockIdx.x * 64;
    __shared__ float As[16][68];
    __shared__ float Ws[16][68];
    const int t  = threadIdx.x;
    const int tx = t % 16, ty = t / 16;
    const int lk = t % 16, lr = t / 16;

    u64 acc2[4][2];
    #pragma unroll
    for (int i = 0; i < 4; i++) {
        acc2[i][0] = pack2(0.f, 0.f);
        acc2[i][1] = pack2(0.f, 0.f);
    }

    for (int kt = 0; kt < HDA; kt += 16) {
        #pragma unroll
        for (int i = 0; i < 4; i++) {
            const int m = i * 16 + lr;
            As[lk][m] = g_Oh[(size_t)(bm + m) * HDA + kt + lk];
            Ws[lk][m] = wo  [(size_t)m        * HDA + kt + lk];
        }
        __syncthreads();
        #pragma unroll
        for (int kk = 0; kk < 16; kk++) {
            float a[4], b[4];
            #pragma unroll
            for (int i = 0; i < 4; i++) a[i] = As[kk][ty * 4 + i];
            #pragma unroll
            for (int j = 0; j < 4; j++) b[j] = Ws[kk][tx + 16 * j];
            const u64 b20 = pack2(b[0], b[1]);
            const u64 b21 = pack2(b[2], b[3]);
            #pragma unroll
            for (int i = 0; i < 4; i++) {
                const u64 a2 = pack2(a[i], a[i]);
                acc2[i][0] = ffma2(a2, b20, acc2[i][0]);
                acc2[i][1] = ffma2(a2, b21, acc2[i][1]);
            }
        }
        __syncthreads();
    }

    #pragma unroll
    for (int i = 0; i < 4; i++) {
        const int m = bm + ty * 4 + i;
        float2 p0 = unpack2(acc2[i][0]), p1 = unpack2(acc2[i][1]);
        out[(size_t)m * HD_ + tx]      = p0.x + bo[tx];
        out[(size_t)m * HD_ + tx + 16] = p0.y + bo[tx + 16];
        out[(size_t)m * HD_ + tx + 32] = p1.x + bo[tx + 32];
        out[(size_t)m * HD_ + tx + 48] = p1.y + bo[tx + 48];
    }
}

// ---------------------------------------------------------------------------
extern "C" void kernel_launch(void* const* d_in, const int* in_sizes, int n_in,
                              void* d_out, int out_size)
{
    (void)in_sizes; (void)n_in; (void)out_size;
    const float* q    = (const float*)d_in[0];
    const float* k    = (const float*)d_in[1];
    const float* v    = (const float*)d_in[2];
    const int*   mask = (const int*)  d_in[3];
    const float* wq   = (const float*)d_in[4];
    const float* bq   = (const float*)d_in[5];
    const float* wk   = (const float*)d_in[6];
    const float* bk   = (const float*)d_in[7];
    const float* wv   = (const float*)d_in[8];
    const float* bv   = (const float*)d_in[9];
    const float* wo   = (const float*)d_in[10];
    const float* bo   = (const float*)d_in[11];

    float* out    = (float*)d_out;                       // [B, LQ, 64]
    float* scores = out + (size_t)B_ * LQ_ * HD_;        // [B, H, LQ, LK]

    __nv_bfloat16 *Xhi, *Xlo, *Whi, *Wlo, *Qhi, *Qlo, *Khi, *Klo;
    float* Vf;
    cudaGetSymbolAddress((void**)&Xhi, g_Xhi);
    cudaGetSymbolAddress((void**)&Xlo, g_Xlo);
    cudaGetSymbolAddress((void**)&Whi, g_Whi);
    cudaGetSymbolAddress((void**)&Wlo, g_Wlo);
    cudaGetSymbolAddress((void**)&Qhi, g_Qhi);
    cudaGetSymbolAddress((void**)&Qlo, g_Qlo);
    cudaGetSymbolAddress((void**)&Khi, g_Khi);
    cudaGetSymbolAddress((void**)&Klo, g_Klo);
    cudaGetSymbolAddress((void**)&Vf,  g_Vf);

    const int QK_SMEM = 4 * 128 * 72 * 2;                // 73728 B
    cudaFuncSetAttribute(qk_stats, cudaFuncAttributeMaxDynamicSharedMemorySize,
                         QK_SMEM);
    cudaFuncSetAttribute(attn_mma, cudaFuncAttributeMaxDynamicSharedMemorySize,
                         ATTN_SMEM);
    cudaFuncSetAttribute(proj_mma, cudaFuncAttributeMaxDynamicSharedMemorySize,
                         PJ_SMEM);

    const dim3 blk(256);
    const int  NX8 = (B_ * LQ_ * IND) / 8;
    const int  NW8 = (IND * IND) / 8;
    const dim3 gproj(IND / 128, (B_ * LQ_) / 128);       // (8, 64)

    split_kernel<<<NX8 / 256, blk>>>(q, Xhi, Xlo, NX8);
    split_kernel<<<NW8 / 256, blk>>>(wq, Whi, Wlo, NW8);
    proj_mma<<<gproj, 512, PJ_SMEM>>>(bq, 0.125f, 1, nullptr, Qhi, Qlo);
    split_kernel<<<NX8 / 256, blk>>>(k, Xhi, Xlo, NX8);
    split_kernel<<<NW8 / 256, blk>>>(wk, Whi, Wlo, NW8);
    proj_mma<<<gproj, 512, PJ_SMEM>>>(bk, 1.0f, 1, nullptr, Khi, Klo);
    split_kernel<<<NX8 / 256, blk>>>(v, Xhi, Xlo, NX8);
    split_kernel<<<NW8 / 256, blk>>>(wv, Whi, Wlo, NW8);
    proj_mma<<<gproj, 512, PJ_SMEM>>>(bv, 1.0f, 0, Vf, nullptr, nullptr);

    vtrans_kernel<<<dim3(LK_ / 64, NZ), blk>>>();        // (32, 64)

    qk_stats<<<dim3(LK_ / 128, LQ_ / 128, NZ), 512, QK_SMEM>>>(mask);

    combine_kernel<<<(NZ * LQ_ + 255) / 256, blk>>>();   // 512 blocks

    attn_mma<<<dim3(LQ_ / 128, NZ), 512, ATTN_SMEM>>>(mask, scores);

    o_kernel<<<(B_ * LQ_) / 64, blk>>>(wo, bo, out);     // 128 blocks
}

// round 16
// speedup vs baseline: 1.1890x; 1.1187x over previous
#include <cuda_runtime.h>
#include <cuda_bf16.h>
#include <math.h>
#include <cstdint>

#define B_   4
#define LQ_  2048
#define LK_  2048
#define IND  1024
#define NH_  16
#define HD_  64
#define HDA  1024
#define NZ   (B_*NH_)
#define NEGV (-1e9f)

typedef unsigned long long u64;

// Scratch (device globals)
__device__ __nv_bfloat16 g_Xhi[(size_t)B_ * LQ_ * IND];
__device__ __nv_bfloat16 g_Xlo[(size_t)B_ * LQ_ * IND];
__device__ __nv_bfloat16 g_Whi[(size_t)IND * IND];
__device__ __nv_bfloat16 g_Wlo[(size_t)IND * IND];
__device__ __nv_bfloat16 g_Qhi[(size_t)NZ * LQ_ * HD_];
__device__ __nv_bfloat16 g_Qlo[(size_t)NZ * LQ_ * HD_];
__device__ __nv_bfloat16 g_Khi[(size_t)NZ * LK_ * HD_];
__device__ __nv_bfloat16 g_Klo[(size_t)NZ * LK_ * HD_];
__device__ __nv_bfloat16 g_Vthi[(size_t)NZ * HD_ * LK_];
__device__ __nv_bfloat16 g_Vtlo[(size_t)NZ * HD_ * LK_];
__device__ float  g_Vf[(size_t)NZ * LK_ * HD_];
__device__ __nv_bfloat16 g_Ohhi[(size_t)B_ * LQ_ * HDA];   // O split hi
__device__ __nv_bfloat16 g_Ohlo[(size_t)B_ * LQ_ * HDA];   // O split lo
__device__ __nv_bfloat16 g_Wohi[(size_t)HD_ * HDA];        // wo split
__device__ __nv_bfloat16 g_Wolo[(size_t)HD_ * HDA];
__device__ float2 g_part[(size_t)NZ * 64 * LQ_];
__device__ float2 g_stats[(size_t)NZ * LQ_];

// ---------------- helpers ----------------
__device__ __forceinline__ uint32_t smem_u32(const void* p) {
    uint32_t a;
    asm("{ .reg .u64 t; cvta.to.shared.u64 t, %1; cvt.u32.u64 %0, t; }" : "=r"(a) : "l"(p));
    return a;
}
__device__ __forceinline__ void cpa16(uint32_t dst, const void* src) {
    asm volatile("cp.async.cg.shared.global [%0], [%1], 16;" :: "r"(dst), "l"(src));
}
#define CP_COMMIT() asm volatile("cp.async.commit_group;" ::: "memory")
#define CP_WAIT0()  asm volatile("cp.async.wait_group 0;" ::: "memory")
#define CP_WAIT1()  asm volatile("cp.async.wait_group 1;" ::: "memory")

__device__ __forceinline__ void ldsm4(uint32_t (&r)[4], uint32_t addr) {
    asm volatile("ldmatrix.sync.aligned.m8n8.x4.shared.b16 {%0,%1,%2,%3}, [%4];"
                 : "=r"(r[0]), "=r"(r[1]), "=r"(r[2]), "=r"(r[3]) : "r"(addr));
}
__device__ __forceinline__ uint32_t fa72(uint32_t base, int row0, int k0, int lane) {
    const int g = lane >> 3;
    const int row = row0 + (lane & 7) + ((g & 1) << 3);
    const int col = k0 + ((g >> 1) << 3);
    return base + (uint32_t)(row * 72 + col) * 2;
}
__device__ __forceinline__ uint32_t fa40(uint32_t base, int row0, int k0, int lane) {
    const int g = lane >> 3;
    const int row = row0 + (lane & 7) + ((g & 1) << 3);
    const int col = k0 + ((g >> 1) << 3);
    return base + (uint32_t)(row * 40 + col) * 2;
}
__device__ __forceinline__ void mma16816(float (&d)[4], const uint32_t (&a)[4],
                                         uint32_t b0, uint32_t b1) {
    asm volatile(
        "mma.sync.aligned.m16n8k16.row.col.f32.bf16.bf16.f32 "
        "{%0,%1,%2,%3},{%4,%5,%6,%7},{%8,%9},{%0,%1,%2,%3};"
        : "+f"(d[0]), "+f"(d[1]), "+f"(d[2]), "+f"(d[3])
        : "r"(a[0]), "r"(a[1]), "r"(a[2]), "r"(a[3]), "r"(b0), "r"(b1));
}
__device__ __forceinline__ void split8(const float* v, uint4& hi, uint4& lo) {
    unsigned short h[8], l[8];
    #pragma unroll
    for (int i = 0; i < 8; i++) {
        __nv_bfloat16 hb = __float2bfloat16_rn(v[i]);
        __nv_bfloat16 lb = __float2bfloat16_rn(v[i] - __bfloat162float(hb));
        h[i] = __bfloat16_as_ushort(hb);
        l[i] = __bfloat16_as_ushort(lb);
    }
    hi.x = h[0] | ((uint32_t)h[1] << 16); hi.y = h[2] | ((uint32_t)h[3] << 16);
    hi.z = h[4] | ((uint32_t)h[5] << 16); hi.w = h[6] | ((uint32_t)h[7] << 16);
    lo.x = l[0] | ((uint32_t)l[1] << 16); lo.y = l[2] | ((uint32_t)l[3] << 16);
    lo.z = l[4] | ((uint32_t)l[5] << 16); lo.w = l[6] | ((uint32_t)l[7] << 16);
}
__device__ __forceinline__ uint32_t splitbf2(float v0, float v1, uint32_t& lo) {
    __nv_bfloat16 h0 = __float2bfloat16_rn(v0);
    __nv_bfloat16 h1 = __float2bfloat16_rn(v1);
    __nv_bfloat16 l0 = __float2bfloat16_rn(v0 - __bfloat162float(h0));
    __nv_bfloat16 l1 = __float2bfloat16_rn(v1 - __bfloat162float(h1));
    lo = (uint32_t)__bfloat16_as_ushort(l0) | ((uint32_t)__bfloat16_as_ushort(l1) << 16);
    return (uint32_t)__bfloat16_as_ushort(h0) | ((uint32_t)__bfloat16_as_ushort(h1) << 16);
}

// ---------------------------------------------------------------------------
// Split fp32 -> bf16 hi/lo (streaming).
// ---------------------------------------------------------------------------
__global__ __launch_bounds__(256) void split_kernel(
    const float* __restrict__ x, __nv_bfloat16* __restrict__ hi,
    __nv_bfloat16* __restrict__ lo, int n8)
{
    const int i = blockIdx.x * 256 + threadIdx.x;
    if (i >= n8) return;
    float v[8];
    *(float4*)v       = *(const float4*)(x + (size_t)i * 8);
    *(float4*)(v + 4) = *(const float4*)(x + (size_t)i * 8 + 4);
    uint4 h, l; split8(v, h, l);
    *(uint4*)(hi + (size_t)i * 8) = h;
    *(uint4*)(lo + (size_t)i * 8) = l;
}

// ---------------------------------------------------------------------------
// Projection via bf16x3 mma.sync (round-13, unchanged).
// ---------------------------------------------------------------------------
#define PJ_TILE(b, tI) ((uint32_t)(((b) * 4 + (tI)) * 5120))
#define PJ_SMEM (8 * 5120 * 2)

__device__ __forceinline__ void proj_load_chunk(
    uint32_t sb, int b, int kt, int t, int bm, int bn)
{
    #pragma unroll
    for (int c = 0; c < 4; c++) {
        const int id = c * 512 + t;
        const int tile = id >> 9;
        const int row = (id >> 2) & 127;
        const int seg = id & 3;
        const __nv_bfloat16* p =
            (tile == 0) ? g_Xhi : (tile == 1) ? g_Xlo :
            (tile == 2) ? g_Whi : g_Wlo;
        const int rb = (tile < 2) ? bm : bn;
        const __nv_bfloat16* src = p + (size_t)(rb + row) * IND + kt + seg * 8;
        cpa16(sb + (PJ_TILE(b, tile) + (uint32_t)(row * 40 + seg * 8)) * 2, src);
    }
}

__global__ __launch_bounds__(512) void proj_mma(
    const float* __restrict__ bias, float alpha, int mode,
    float* __restrict__ dstF,
    __nv_bfloat16* __restrict__ dstHi, __nv_bfloat16* __restrict__ dstLo)
{
    extern __shared__ __align__(16) unsigned short sm[];
    const uint32_t sb = smem_u32(sm);
    const int t = threadIdx.x, lane = t & 31, w = t >> 5;
    const int wm = w >> 2, wn = w & 3;
    const int bm = blockIdx.y * 128, bn = blockIdx.x * 128;

    float acc[2][4][4];
    #pragma unroll
    for (int i = 0; i < 2; i++)
        #pragma unroll
        for (int j = 0; j < 4; j++)
            #pragma unroll
            for (int q = 0; q < 4; q++) acc[i][j][q] = 0.f;

    proj_load_chunk(sb, 0, 0, t, bm, bn);
    CP_COMMIT();

    for (int it = 0; it < 32; it++) {
        if (it + 1 < 32) {
            proj_load_chunk(sb, (it + 1) & 1, (it + 1) * 32, t, bm, bn);
            CP_COMMIT();
            CP_WAIT1();
        } else {
            CP_WAIT0();
        }
        __syncthreads();
        const int b = it & 1;
        const uint32_t ah = sb + PJ_TILE(b, 0) * 2, al = sb + PJ_TILE(b, 1) * 2;
        const uint32_t bh = sb + PJ_TILE(b, 2) * 2, bl = sb + PJ_TILE(b, 3) * 2;
        #pragma unroll
        for (int k16 = 0; k16 < 2; k16++) {
            const int k0 = k16 * 16;
            uint32_t afh[2][4], afl[2][4], bfh[2][4], bfl[2][4];
            #pragma unroll
            for (int mi = 0; mi < 2; mi++) {
                ldsm4(afh[mi], fa40(ah, wm * 32 + mi * 16, k0, lane));
                ldsm4(afl[mi], fa40(al, wm * 32 + mi * 16, k0, lane));
            }
            #pragma unroll
            for (int ng = 0; ng < 2; ng++) {
                ldsm4(bfh[ng], fa40(bh, wn * 32 + ng * 16, k0, lane));
                ldsm4(bfl[ng], fa40(bl, wn * 32 + ng * 16, k0, lane));
            }
            #pragma unroll
            for (int mi = 0; mi < 2; mi++)
                #pragma unroll
                for (int nj = 0; nj < 4; nj++) {
                    const int ng = nj >> 1, hh = nj & 1;
                    mma16816(acc[mi][nj], afh[mi], bfh[ng][hh], bfh[ng][hh + 2]);
                    mma16816(acc[mi][nj], afh[mi], bfl[ng][hh], bfl[ng][hh + 2]);
                    mma16816(acc[mi][nj], afl[mi], bfh[ng][hh], bfh[ng][hh + 2]);
                }
        }
        __syncthreads();
    }

    #pragma unroll
    for (int mi = 0; mi < 2; mi++)
        #pragma unroll
        for (int half = 0; half < 2; half++) {
            const int m = bm + wm * 32 + mi * 16 + (lane >> 2) + half * 8;
            const int bb = m >> 11, l = m & 2047;
            #pragma unroll
            for (int nj = 0; nj < 4; nj++) {
                const int c = bn + wn * 32 + nj * 8 + (lane & 3) * 2;
                const int h = c >> 6, dd = c & 63;
                const size_t idx =
                    (((size_t)(bb * NH_ + h)) * 2048 + l) * 64 + dd;
                const float v0 = alpha * (acc[mi][nj][half * 2]     + bias[c]);
                const float v1 = alpha * (acc[mi][nj][half * 2 + 1] + bias[c + 1]);
                if (mode == 0) {
                    *(float2*)&dstF[idx] = make_float2(v0, v1);
                } else {
                    uint32_t lo;
                    const uint32_t hi = splitbf2(v0, v1, lo);
                    *(uint32_t*)&dstHi[idx] = hi;
                    *(uint32_t*)&dstLo[idx] = lo;
                }
            }
        }
}

// ---------------------------------------------------------------------------
// V transpose (unchanged).
// ---------------------------------------------------------------------------
__global__ __launch_bounds__(256) void vtrans_kernel()
{
    const int z = blockIdx.y, l0 = blockIdx.x * 64;
    __shared__ float tile[64][65];
    const int t = threadIdx.x, row = t >> 2, q = t & 3;
    #pragma unroll
    for (int i = 0; i < 4; i++) {
        float4 v = *(const float4*)&g_Vf[((size_t)z * 2048 + l0 + row) * 64 + q * 16 + i * 4];
        tile[row][q * 16 + i * 4 + 0] = v.x;
        tile[row][q * 16 + i * 4 + 1] = v.y;
        tile[row][q * 16 + i * 4 + 2] = v.z;
        tile[row][q * 16 + i * 4 + 3] = v.w;
    }
    __syncthreads();
    float v[16];
    #pragma unroll
    for (int i = 0; i < 16; i++) v[i] = tile[q * 16 + i][row];
    uint4 h0, l0v, h1, l1;
    split8(v, h0, l0v); split8(v + 8, h1, l1);
    const size_t base = ((size_t)z * 64 + row) * 2048 + l0 + q * 16;
    *(uint4*)&g_Vthi[base]     = h0;  *(uint4*)&g_Vthi[base + 8] = h1;
    *(uint4*)&g_Vtlo[base]     = l0v; *(uint4*)&g_Vtlo[base + 8] = l1;
}

// ---------------------------------------------------------------------------
// QK^T via bf16x3 mma.sync (round-10/13 version, unchanged).
// ---------------------------------------------------------------------------
__global__ __launch_bounds__(512) void qk_mma(
    const int* __restrict__ mask, float* __restrict__ S)
{
    extern __shared__ __align__(16) unsigned short sm[];
    const uint32_t sb = smem_u32(sm);
    const int t = threadIdx.x, lane = t & 31, w = t >> 5;
    const int wm = w >> 2, wn = w & 3;
    const int z = blockIdx.z, bm = blockIdx.y * 128, bn = blockIdx.x * 128;

    const uint32_t qh = sb, ql = sb + 9216*2, kh = sb + 18432*2, kl = sb + 27648*2;

    #pragma unroll
    for (int c = 0; c < 8; c++) {
        const int id   = c * 512 + t;
        const int tile = id >> 10;
        const int row  = (id >> 3) & 127;
        const int seg  = id & 7;
        const __nv_bfloat16* p0 =
            (tile == 0) ? g_Qhi : (tile == 1) ? g_Qlo :
            (tile == 2) ? g_Khi : g_Klo;
        const int rb = (tile < 2) ? bm : bn;
        const __nv_bfloat16* src =
            p0 + ((size_t)z * 2048 + rb + row) * 64 + seg * 8;
        const uint32_t dst = sb + (uint32_t)(tile * 9216 + row * 72 + seg * 8) * 2;
        cpa16(dst, src);
    }
    CP_COMMIT();
    CP_WAIT0();
    __syncthreads();

    float acc[2][4][4];
    #pragma unroll
    for (int i = 0; i < 2; i++)
        #pragma unroll
        for (int j = 0; j < 4; j++)
            #pragma unroll
            for (int q = 0; q < 4; q++) acc[i][j][q] = 0.f;

    #pragma unroll
    for (int k16 = 0; k16 < 4; k16++) {
        const int k0 = k16 * 16;
        uint32_t afh[2][4], afl[2][4], bfh[2][4], bfl[2][4];
        #pragma unroll
        for (int mi = 0; mi < 2; mi++) {
            ldsm4(afh[mi], fa72(qh, wm * 32 + mi * 16, k0, lane));
            ldsm4(afl[mi], fa72(ql, wm * 32 + mi * 16, k0, lane));
        }
        #pragma unroll
        for (int ng = 0; ng < 2; ng++) {
            ldsm4(bfh[ng], fa72(kh, wn * 32 + ng * 16, k0, lane));
            ldsm4(bfl[ng], fa72(kl, wn * 32 + ng * 16, k0, lane));
        }
        #pragma unroll
        for (int mi = 0; mi < 2; mi++)
            #pragma unroll
            for (int nj = 0; nj < 4; nj++) {
                const int ng = nj >> 1, hh = nj & 1;
                mma16816(acc[mi][nj], afh[mi], bfh[ng][hh], bfh[ng][hh + 2]);
                mma16816(acc[mi][nj], afh[mi], bfl[ng][hh], bfl[ng][hh + 2]);
                mma16816(acc[mi][nj], afl[mi], bfh[ng][hh], bfh[ng][hh + 2]);
            }
    }

    float* Sz = S + (size_t)z * LQ_ * LK_;
    float2* part = g_part + ((size_t)z * 64 + blockIdx.x * 4 + wn) * LQ_;
    #pragma unroll
    for (int mi = 0; mi < 2; mi++)
        #pragma unroll
        for (int half = 0; half < 2; half++) {
            const int r = bm + wm * 32 + mi * 16 + (lane >> 2) + half * 8;
            float v[8];
            #pragma unroll
            for (int nj = 0; nj < 4; nj++) {
                const int c = bn + wn * 32 + nj * 8 + (lane & 3) * 2;
                const int2 mm = *(const int2*)&mask[(size_t)r * LK_ + c];
                v[nj * 2]     = mm.x ? acc[mi][nj][half * 2]     : NEGV;
                v[nj * 2 + 1] = mm.y ? acc[mi][nj][half * 2 + 1] : NEGV;
                *(float2*)&Sz[(size_t)r * LK_ + c] =
                    make_float2(v[nj * 2], v[nj * 2 + 1]);
            }
            float mx = v[0];
            #pragma unroll
            for (int j = 1; j < 8; j++) mx = fmaxf(mx, v[j]);
            mx = fmaxf(mx, __shfl_xor_sync(0xffffffffu, mx, 1));
            mx = fmaxf(mx, __shfl_xor_sync(0xffffffffu, mx, 2));
            float smv = 0.f;
            #pragma unroll
            for (int j = 0; j < 8; j++) smv += __expf(v[j] - mx);
            smv += __shfl_xor_sync(0xffffffffu, smv, 1);
            smv += __shfl_xor_sync(0xffffffffu, smv, 2);
            if ((lane & 3) == 0) part[r] = make_float2(mx, smv);
        }
}

// ---------------------------------------------------------------------------
// Combine 64 partial stats per row -> {rowmax, 1/rowsum}.
// ---------------------------------------------------------------------------
__global__ __launch_bounds__(256) void combine_kernel()
{
    const int idx = blockIdx.x * 256 + threadIdx.x;
    if (idx >= NZ * LQ_) return;
    const int z = idx >> 11, m = idx & 2047;
    const float2* p = g_part + (size_t)z * 64 * LQ_ + m;
    float M = -3.4e38f;
    #pragma unroll 8
    for (int i = 0; i < 64; i++) M = fmaxf(M, p[(size_t)i * LQ_].x);
    float Ssum = 0.f;
    #pragma unroll 8
    for (int i = 0; i < 64; i++) {
        const float2 q = p[(size_t)i * LQ_];
        Ssum += q.y * __expf(q.x - M);
    }
    g_stats[idx] = make_float2(M, 1.0f / Ssum);
}

// ---------------------------------------------------------------------------
// PV via bf16x3 mma.sync with register S-prefetch (round-13) — epilogue now
// writes O as bf16 hi/lo for the HMMA output GEMM.
// ---------------------------------------------------------------------------
#define PV_P(b, h)  ((uint32_t)(((b) * 2 + (h)) * 5120))
#define PV_V(b, h)  ((uint32_t)(20480 + ((b) * 2 + (h)) * 2560))
#define PV_SMEM     ((20480 + 4 * 2560) * 2)

__global__ __launch_bounds__(256) void pv_mma(float* __restrict__ S)
{
    extern __shared__ __align__(16) unsigned short sm[];
    const uint32_t sb = smem_u32(sm);
    const int t = threadIdx.x, lane = t & 31, w = t >> 5;
    const int wm = w >> 1, wn = w & 1;
    const int z = blockIdx.y, bm = blockIdx.x * 128;

    const int r = t >> 1, half = t & 1;
    const float2 st = g_stats[(size_t)z * LQ_ + bm + r];
    float* Sr = S + (size_t)z * LQ_ * LK_ + (size_t)(bm + r) * LK_;

    const __nv_bfloat16* Vh0 = g_Vthi + (size_t)z * 64 * 2048;
    const __nv_bfloat16* Vl0 = g_Vtlo + (size_t)z * 64 * 2048;

    float acc[2][4][4];
    #pragma unroll
    for (int i = 0; i < 2; i++)
        #pragma unroll
        for (int j = 0; j < 4; j++)
            #pragma unroll
            for (int q = 0; q < 4; q++) acc[i][j][q] = 0.f;

    {
        #pragma unroll
        for (int c = 0; c < 2; c++) {
            const int id = c * 256 + t;
            const int hl = id >> 8;
            const int row = (id >> 2) & 63;
            const int seg = id & 3;
            const __nv_bfloat16* src =
                (hl ? Vl0 : Vh0) + (size_t)row * 2048 + 0 + seg * 8;
            cpa16(sb + (PV_V(0, hl) + (uint32_t)(row * 40 + seg * 8)) * 2, src);
        }
        CP_COMMIT();
    }
    float sreg[16];
    {
        const float* sp = Sr + half * 16;
        *(float4*)(sreg)      = *(const float4*)(sp);
        *(float4*)(sreg + 4)  = *(const float4*)(sp + 4);
        *(float4*)(sreg + 8)  = *(const float4*)(sp + 8);
        *(float4*)(sreg + 12) = *(const float4*)(sp + 12);
    }

    for (int it = 0; it < 64; it++) {
        const int kt = it * 32;
        const int pb = it & 1;
        {
            uint4 hi, lo;
            #pragma unroll
            for (int s = 0; s < 2; s++) {
                float v[8];
                #pragma unroll
                for (int j = 0; j < 8; j++)
                    v[j] = __expf(sreg[s * 8 + j] - st.x) * st.y;
                float* sp = Sr + kt + half * 16 + s * 8;
                *(float4*)(sp)     = make_float4(v[0], v[1], v[2], v[3]);
                *(float4*)(sp + 4) = make_float4(v[4], v[5], v[6], v[7]);
                split8(v, hi, lo);
                const uint32_t off = (uint32_t)(r * 40 + half * 16 + s * 8) * 2;
                *(uint4*)((char*)sm + (PV_P(pb, 0)) * 2 + off) = hi;
                *(uint4*)((char*)sm + (PV_P(pb, 1)) * 2 + off) = lo;
            }
        }
        if (it + 1 < 64) {
            const float* sp = Sr + (it + 1) * 32 + half * 16;
            *(float4*)(sreg)      = *(const float4*)(sp);
            *(float4*)(sreg + 4)  = *(const float4*)(sp + 4);
            *(float4*)(sreg + 8)  = *(const float4*)(sp + 8);
            *(float4*)(sreg + 12) = *(const float4*)(sp + 12);
        }
        if (it + 1 < 64) {
            const int vb = (it + 1) & 1;
            const int kn = (it + 1) * 32;
            #pragma unroll
            for (int c = 0; c < 2; c++) {
                const int id = c * 256 + t;
                const int hl = id >> 8;
                const int row = (id >> 2) & 63;
                const int seg = id & 3;
                const __nv_bfloat16* src =
                    (hl ? Vl0 : Vh0) + (size_t)row * 2048 + kn + seg * 8;
                cpa16(sb + (PV_V(vb, hl) + (uint32_t)(row * 40 + seg * 8)) * 2, src);
            }
            CP_COMMIT();
            CP_WAIT1();
        } else {
            CP_WAIT0();
        }
        __syncthreads();

        const uint32_t ph = sb + PV_P(pb, 0) * 2, pl = sb + PV_P(pb, 1) * 2;
        const uint32_t vh = sb + PV_V(pb, 0) * 2, vl = sb + PV_V(pb, 1) * 2;
        #pragma unroll
        for (int k16 = 0; k16 < 2; k16++) {
            const int k0 = k16 * 16;
            uint32_t afh[2][4], afl[2][4], bfh[2][4], bfl[2][4];
            #pragma unroll
            for (int mi = 0; mi < 2; mi++) {
                ldsm4(afh[mi], fa40(ph, wm * 32 + mi * 16, k0, lane));
                ldsm4(afl[mi], fa40(pl, wm * 32 + mi * 16, k0, lane));
            }
            #pragma unroll
            for (int ng = 0; ng < 2; ng++) {
                ldsm4(bfh[ng], fa40(vh, wn * 32 + ng * 16, k0, lane));
                ldsm4(bfl[ng], fa40(vl, wn * 32 + ng * 16, k0, lane));
            }
            #pragma unroll
            for (int mi = 0; mi < 2; mi++)
                #pragma unroll
                for (int nj = 0; nj < 4; nj++) {
                    const int ng = nj >> 1, hh = nj & 1;
                    mma16816(acc[mi][nj], afh[mi], bfh[ng][hh], bfh[ng][hh + 2]);
                    mma16816(acc[mi][nj], afh[mi], bfl[ng][hh], bfl[ng][hh + 2]);
                    mma16816(acc[mi][nj], afl[mi], bfh[ng][hh], bfh[ng][hh + 2]);
                }
        }
        __syncthreads();
    }

    const int bb = z >> 4, h = z & 15;
    #pragma unroll
    for (int mi = 0; mi < 2; mi++)
        #pragma unroll
        for (int nj = 0; nj < 4; nj++) {
            const int r0 = bm + wm * 32 + mi * 16 + (lane >> 2);
            const int c  = wn * 32 + nj * 8 + (lane & 3) * 2;
            #pragma unroll
            for (int hf = 0; hf < 2; hf++) {
                const int rr = r0 + hf * 8;
                const size_t idx = ((size_t)bb * LQ_ + rr) * HDA + h * 64 + c;
                uint32_t lo;
                const uint32_t hi = splitbf2(acc[mi][nj][hf * 2],
                                             acc[mi][nj][hf * 2 + 1], lo);
                *(uint32_t*)&g_Ohhi[idx] = hi;
                *(uint32_t*)&g_Ohlo[idx] = lo;
            }
        }
}

// ---------------------------------------------------------------------------
// Output GEMM via bf16x3 HMMA: out = Oh @ wo^T + bo.
// CTA 128(M) x 64(N), 512 threads (16 warps, 4m x 4n), K=1024 in 32-chunks.
// smem: A(hi,lo)x2 [128][40], B(hi,lo)x2 [64][40] = 61440 B.
// ---------------------------------------------------------------------------
#define OA(b, arr) ((uint32_t)(((b) * 2 + (arr)) * 5120))
#define OB(b, arr) ((uint32_t)(20480 + ((b) * 2 + (arr)) * 2560))
#define O_SMEM     61440

__device__ __forceinline__ void o_load_chunk(
    uint32_t sb, int b, int kt, int t, int bm)
{
    #pragma unroll
    for (int c = 0; c < 3; c++) {
        const int id = c * 512 + t;
        if (id < 1024) {
            const int arr = id >> 9;
            const int row = (id >> 2) & 127;
            const int seg = id & 3;
            const __nv_bfloat16* src =
                (arr ? g_Ohlo : g_Ohhi) + (size_t)(bm + row) * HDA + kt + seg * 8;
            cpa16(sb + (OA(b, arr) + (uint32_t)(row * 40 + seg * 8)) * 2, src);
        } else {
            const int id2 = id - 1024;
            const int arr = id2 >> 8;
            const int row = (id2 >> 2) & 63;
            const int seg = id2 & 3;
            const __nv_bfloat16* src =
                (arr ? g_Wolo : g_Wohi) + (size_t)row * HDA + kt + seg * 8;
            cpa16(sb + (OB(b, arr) + (uint32_t)(row * 40 + seg * 8)) * 2, src);
        }
    }
}

__global__ __launch_bounds__(512) void o_mma(
    const float* __restrict__ bo, float* __restrict__ out)
{
    extern __shared__ __align__(16) unsigned short sm[];
    const uint32_t sb = smem_u32(sm);
    const int t = threadIdx.x, lane = t & 31, w = t >> 5;
    const int wm = w >> 2, wn = w & 3;
    const int bm = blockIdx.x * 128;

    float acc[2][2][4];
    #pragma unroll
    for (int i = 0; i < 2; i++)
        #pragma unroll
        for (int j = 0; j < 2; j++)
            #pragma unroll
            for (int q = 0; q < 4; q++) acc[i][j][q] = 0.f;

    o_load_chunk(sb, 0, 0, t, bm);
    CP_COMMIT();

    for (int it = 0; it < 32; it++) {
        if (it + 1 < 32) {
            o_load_chunk(sb, (it + 1) & 1, (it + 1) * 32, t, bm);
            CP_COMMIT();
            CP_WAIT1();
        } else {
            CP_WAIT0();
        }
        __syncthreads();
        const int b = it & 1;
        const uint32_t ah = sb + OA(b, 0) * 2, al = sb + OA(b, 1) * 2;
        const uint32_t bh = sb + OB(b, 0) * 2, bl = sb + OB(b, 1) * 2;
        #pragma unroll
        for (int k16 = 0; k16 < 2; k16++) {
            const int k0 = k16 * 16;
            uint32_t afh[2][4], afl[2][4], bfh[4], bfl[4];
            #pragma unroll
            for (int mi = 0; mi < 2; mi++) {
                ldsm4(afh[mi], fa40(ah, wm * 32 + mi * 16, k0, lane));
                ldsm4(afl[mi], fa40(al, wm * 32 + mi * 16, k0, lane));
            }
            ldsm4(bfh, fa40(bh, wn * 16, k0, lane));
            ldsm4(bfl, fa40(bl, wn * 16, k0, lane));
            #pragma unroll
            for (int mi = 0; mi < 2; mi++)
                #pragma unroll
                for (int nj = 0; nj < 2; nj++) {
                    mma16816(acc[mi][nj], afh[mi], bfh[nj], bfh[nj + 2]);
                    mma16816(acc[mi][nj], afh[mi], bfl[nj], bfl[nj + 2]);
                    mma16816(acc[mi][nj], afl[mi], bfh[nj], bfh[nj + 2]);
                }
        }
        __syncthreads();
    }

    #pragma unroll
    for (int mi = 0; mi < 2; mi++)
        #pragma unroll
        for (int hf = 0; hf < 2; hf++) {
            const int m = bm + wm * 32 + mi * 16 + (lane >> 2) + hf * 8;
            #pragma unroll
            for (int nj = 0; nj < 2; nj++) {
                const int c = wn * 16 + nj * 8 + (lane & 3) * 2;
                *(float2*)&out[(size_t)m * HD_ + c] = make_float2(
                    acc[mi][nj][hf * 2]     + bo[c],
                    acc[mi][nj][hf * 2 + 1] + bo[c + 1]);
            }
        }
}

// ---------------------------------------------------------------------------
extern "C" void kernel_launch(void* const* d_in, const int* in_sizes, int n_in,
                              void* d_out, int out_size)
{
    (void)in_sizes; (void)n_in; (void)out_size;
    const float* q    = (const float*)d_in[0];
    const float* k    = (const float*)d_in[1];
    const float* v    = (const float*)d_in[2];
    const int*   mask = (const int*)  d_in[3];
    const float* wq   = (const float*)d_in[4];
    const float* bq   = (const float*)d_in[5];
    const float* wk   = (const float*)d_in[6];
    const float* bk   = (const float*)d_in[7];
    const float* wv   = (const float*)d_in[8];
    const float* bv   = (const float*)d_in[9];
    const float* wo   = (const float*)d_in[10];
    const float* bo   = (const float*)d_in[11];

    float* out    = (float*)d_out;                       // [B, LQ, 64]
    float* scores = out + (size_t)B_ * LQ_ * HD_;        // [B, H, LQ, LK]

    __nv_bfloat16 *Xhi, *Xlo, *Whi, *Wlo, *Qhi, *Qlo, *Khi, *Klo, *Wohi, *Wolo;
    float* Vf;
    cudaGetSymbolAddress((void**)&Xhi, g_Xhi);
    cudaGetSymbolAddress((void**)&Xlo, g_Xlo);
    cudaGetSymbolAddress((void**)&Whi, g_Whi);
    cudaGetSymbolAddress((void**)&Wlo, g_Wlo);
    cudaGetSymbolAddress((void**)&Qhi, g_Qhi);
    cudaGetSymbolAddress((void**)&Qlo, g_Qlo);
    cudaGetSymbolAddress((void**)&Khi, g_Khi);
    cudaGetSymbolAddress((void**)&Klo, g_Klo);
    cudaGetSymbolAddress((void**)&Wohi, g_Wohi);
    cudaGetSymbolAddress((void**)&Wolo, g_Wolo);
    cudaGetSymbolAddress((void**)&Vf,  g_Vf);

    const int QK_SMEM = 4 * 128 * 72 * 2;                // 73728 B
    cudaFuncSetAttribute(qk_mma, cudaFuncAttributeMaxDynamicSharedMemorySize,
                         QK_SMEM);
    cudaFuncSetAttribute(pv_mma, cudaFuncAttributeMaxDynamicSharedMemorySize,
                         PV_SMEM);
    cudaFuncSetAttribute(proj_mma, cudaFuncAttributeMaxDynamicSharedMemorySize,
                         PJ_SMEM);
    cudaFuncSetAttribute(o_mma, cudaFuncAttributeMaxDynamicSharedMemorySize,
                         O_SMEM);

    const dim3 blk(256);
    const int  NX8 = (B_ * LQ_ * IND) / 8;
    const int  NW8 = (IND * IND) / 8;
    const int  NWO8 = (HD_ * HDA) / 8;                   // 8192
    const dim3 gproj(IND / 128, (B_ * LQ_) / 128);       // (8, 64)

    split_kernel<<<NX8 / 256, blk>>>(q, Xhi, Xlo, NX8);
    split_kernel<<<NW8 / 256, blk>>>(wq, Whi, Wlo, NW8);
    proj_mma<<<gproj, 512, PJ_SMEM>>>(bq, 0.125f, 1, nullptr, Qhi, Qlo);
    split_kernel<<<NX8 / 256, blk>>>(k, Xhi, Xlo, NX8);
    split_kernel<<<NW8 / 256, blk>>>(wk, Whi, Wlo, NW8);
    proj_mma<<<gproj, 512, PJ_SMEM>>>(bk, 1.0f, 1, nullptr, Khi, Klo);
    split_kernel<<<NX8 / 256, blk>>>(v, Xhi, Xlo, NX8);
    split_kernel<<<NW8 / 256, blk>>>(wv, Whi, Wlo, NW8);
    proj_mma<<<gproj, 512, PJ_SMEM>>>(bv, 1.0f, 0, Vf, nullptr, nullptr);

    split_kernel<<<NWO8 / 256, blk>>>(wo, Wohi, Wolo, NWO8);

    vtrans_kernel<<<dim3(LK_ / 64, NZ), blk>>>();        // (32, 64)

    qk_mma<<<dim3(LK_ / 128, LQ_ / 128, NZ), 512, QK_SMEM>>>(mask, scores);

    combine_kernel<<<(NZ * LQ_ + 255) / 256, blk>>>();   // 512 blocks

    pv_mma<<<dim3(LQ_ / 128, NZ), blk, PV_SMEM>>>(scores);

    o_mma<<<(B_ * LQ_) / 128, 512, O_SMEM>>>(bo, out);   // 64 blocks
}

// round 17
// speedup vs baseline: 1.3366x; 1.1242x over previous
#include <cuda_runtime.h>
#include <cuda_bf16.h>
#include <math.h>
#include <cstdint>

#define B_   4
#define LQ_  2048
#define LK_  2048
#define IND  1024
#define NH_  16
#define HD_  64
#define HDA  1024
#define NZ   (B_*NH_)
#define NEGV (-1e9f)

typedef unsigned long long u64;

// Scratch (device globals)
__device__ __nv_bfloat16 g_Xhi[(size_t)B_ * LQ_ * IND];
__device__ __nv_bfloat16 g_Xlo[(size_t)B_ * LQ_ * IND];
__device__ __nv_bfloat16 g_Whi[(size_t)IND * IND];
__device__ __nv_bfloat16 g_Wlo[(size_t)IND * IND];
__device__ __nv_bfloat16 g_Qhi[(size_t)NZ * LQ_ * HD_];
__device__ __nv_bfloat16 g_Qlo[(size_t)NZ * LQ_ * HD_];
__device__ __nv_bfloat16 g_Khi[(size_t)NZ * LK_ * HD_];
__device__ __nv_bfloat16 g_Klo[(size_t)NZ * LK_ * HD_];
__device__ __nv_bfloat16 g_Vthi[(size_t)NZ * HD_ * LK_];
__device__ __nv_bfloat16 g_Vtlo[(size_t)NZ * HD_ * LK_];
__device__ float  g_Vf[(size_t)NZ * LK_ * HD_];
__device__ __nv_bfloat16 g_Ohhi[(size_t)B_ * LQ_ * HDA];   // O split hi
__device__ __nv_bfloat16 g_Ohlo[(size_t)B_ * LQ_ * HDA];   // O split lo
__device__ __nv_bfloat16 g_Wohi[(size_t)HD_ * HDA];        // wo split
__device__ __nv_bfloat16 g_Wolo[(size_t)HD_ * HDA];
__device__ float2 g_part[(size_t)NZ * 64 * LQ_];
__device__ float2 g_stats[(size_t)NZ * LQ_];

// ---------------- helpers ----------------
__device__ __forceinline__ uint32_t smem_u32(const void* p) {
    uint32_t a;
    asm("{ .reg .u64 t; cvta.to.shared.u64 t, %1; cvt.u32.u64 %0, t; }" : "=r"(a) : "l"(p));
    return a;
}
__device__ __forceinline__ void cpa16(uint32_t dst, const void* src) {
    asm volatile("cp.async.cg.shared.global [%0], [%1], 16;" :: "r"(dst), "l"(src));
}
#define CP_COMMIT() asm volatile("cp.async.commit_group;" ::: "memory")
#define CP_WAIT0()  asm volatile("cp.async.wait_group 0;" ::: "memory")
#define CP_WAIT1()  asm volatile("cp.async.wait_group 1;" ::: "memory")

__device__ __forceinline__ void ldsm4(uint32_t (&r)[4], uint32_t addr) {
    asm volatile("ldmatrix.sync.aligned.m8n8.x4.shared.b16 {%0,%1,%2,%3}, [%4];"
                 : "=r"(r[0]), "=r"(r[1]), "=r"(r[2]), "=r"(r[3]) : "r"(addr));
}
__device__ __forceinline__ uint32_t fa72(uint32_t base, int row0, int k0, int lane) {
    const int g = lane >> 3;
    const int row = row0 + (lane & 7) + ((g & 1) << 3);
    const int col = k0 + ((g >> 1) << 3);
    return base + (uint32_t)(row * 72 + col) * 2;
}
__device__ __forceinline__ uint32_t fa40(uint32_t base, int row0, int k0, int lane) {
    const int g = lane >> 3;
    const int row = row0 + (lane & 7) + ((g & 1) << 3);
    const int col = k0 + ((g >> 1) << 3);
    return base + (uint32_t)(row * 40 + col) * 2;
}
__device__ __forceinline__ void mma16816(float (&d)[4], const uint32_t (&a)[4],
                                         uint32_t b0, uint32_t b1) {
    asm volatile(
        "mma.sync.aligned.m16n8k16.row.col.f32.bf16.bf16.f32 "
        "{%0,%1,%2,%3},{%4,%5,%6,%7},{%8,%9},{%0,%1,%2,%3};"
        : "+f"(d[0]), "+f"(d[1]), "+f"(d[2]), "+f"(d[3])
        : "r"(a[0]), "r"(a[1]), "r"(a[2]), "r"(a[3]), "r"(b0), "r"(b1));
}
__device__ __forceinline__ void split8(const float* v, uint4& hi, uint4& lo) {
    unsigned short h[8], l[8];
    #pragma unroll
    for (int i = 0; i < 8; i++) {
        __nv_bfloat16 hb = __float2bfloat16_rn(v[i]);
        __nv_bfloat16 lb = __float2bfloat16_rn(v[i] - __bfloat162float(hb));
        h[i] = __bfloat16_as_ushort(hb);
        l[i] = __bfloat16_as_ushort(lb);
    }
    hi.x = h[0] | ((uint32_t)h[1] << 16); hi.y = h[2] | ((uint32_t)h[3] << 16);
    hi.z = h[4] | ((uint32_t)h[5] << 16); hi.w = h[6] | ((uint32_t)h[7] << 16);
    lo.x = l[0] | ((uint32_t)l[1] << 16); lo.y = l[2] | ((uint32_t)l[3] << 16);
    lo.z = l[4] | ((uint32_t)l[5] << 16); lo.w = l[6] | ((uint32_t)l[7] << 16);
}
__device__ __forceinline__ uint32_t splitbf2(float v0, float v1, uint32_t& lo) {
    __nv_bfloat16 h0 = __float2bfloat16_rn(v0);
    __nv_bfloat16 h1 = __float2bfloat16_rn(v1);
    __nv_bfloat16 l0 = __float2bfloat16_rn(v0 - __bfloat162float(h0));
    __nv_bfloat16 l1 = __float2bfloat16_rn(v1 - __bfloat162float(h1));
    lo = (uint32_t)__bfloat16_as_ushort(l0) | ((uint32_t)__bfloat16_as_ushort(l1) << 16);
    return (uint32_t)__bfloat16_as_ushort(h0) | ((uint32_t)__bfloat16_as_ushort(h1) << 16);
}

// ---------------------------------------------------------------------------
// Split fp32 -> bf16 hi/lo (streaming).
// ---------------------------------------------------------------------------
__global__ __launch_bounds__(256) void split_kernel(
    const float* __restrict__ x, __nv_bfloat16* __restrict__ hi,
    __nv_bfloat16* __restrict__ lo, int n8)
{
    const int i = blockIdx.x * 256 + threadIdx.x;
    if (i >= n8) return;
    float v[8];
    *(float4*)v       = *(const float4*)(x + (size_t)i * 8);
    *(float4*)(v + 4) = *(const float4*)(x + (size_t)i * 8 + 4);
    uint4 h, l; split8(v, h, l);
    *(uint4*)(hi + (size_t)i * 8) = h;
    *(uint4*)(lo + (size_t)i * 8) = l;
}

// ---------------------------------------------------------------------------
// Projection via bf16x3 mma.sync (round-13 + 2-CTA launch bound).
// ---------------------------------------------------------------------------
#define PJ_TILE(b, tI) ((uint32_t)(((b) * 4 + (tI)) * 5120))
#define PJ_SMEM (8 * 5120 * 2)

__device__ __forceinline__ void proj_load_chunk(
    uint32_t sb, int b, int kt, int t, int bm, int bn)
{
    #pragma unroll
    for (int c = 0; c < 4; c++) {
        const int id = c * 512 + t;
        const int tile = id >> 9;
        const int row = (id >> 2) & 127;
        const int seg = id & 3;
        const __nv_bfloat16* p =
            (tile == 0) ? g_Xhi : (tile == 1) ? g_Xlo :
            (tile == 2) ? g_Whi : g_Wlo;
        const int rb = (tile < 2) ? bm : bn;
        const __nv_bfloat16* src = p + (size_t)(rb + row) * IND + kt + seg * 8;
        cpa16(sb + (PJ_TILE(b, tile) + (uint32_t)(row * 40 + seg * 8)) * 2, src);
    }
}

__global__ __launch_bounds__(512, 2) void proj_mma(
    const float* __restrict__ bias, float alpha, int mode,
    float* __restrict__ dstF,
    __nv_bfloat16* __restrict__ dstHi, __nv_bfloat16* __restrict__ dstLo)
{
    extern __shared__ __align__(16) unsigned short sm[];
    const uint32_t sb = smem_u32(sm);
    const int t = threadIdx.x, lane = t & 31, w = t >> 5;
    const int wm = w >> 2, wn = w & 3;
    const int bm = blockIdx.y * 128, bn = blockIdx.x * 128;

    float acc[2][4][4];
    #pragma unroll
    for (int i = 0; i < 2; i++)
        #pragma unroll
        for (int j = 0; j < 4; j++)
            #pragma unroll
            for (int q = 0; q < 4; q++) acc[i][j][q] = 0.f;

    proj_load_chunk(sb, 0, 0, t, bm, bn);
    CP_COMMIT();

    for (int it = 0; it < 32; it++) {
        if (it + 1 < 32) {
            proj_load_chunk(sb, (it + 1) & 1, (it + 1) * 32, t, bm, bn);
            CP_COMMIT();
            CP_WAIT1();
        } else {
            CP_WAIT0();
        }
        __syncthreads();
        const int b = it & 1;
        const uint32_t ah = sb + PJ_TILE(b, 0) * 2, al = sb + PJ_TILE(b, 1) * 2;
        const uint32_t bh = sb + PJ_TILE(b, 2) * 2, bl = sb + PJ_TILE(b, 3) * 2;
        #pragma unroll
        for (int k16 = 0; k16 < 2; k16++) {
            const int k0 = k16 * 16;
            uint32_t afh[2][4], afl[2][4], bfh[2][4], bfl[2][4];
            #pragma unroll
            for (int mi = 0; mi < 2; mi++) {
                ldsm4(afh[mi], fa40(ah, wm * 32 + mi * 16, k0, lane));
                ldsm4(afl[mi], fa40(al, wm * 32 + mi * 16, k0, lane));
            }
            #pragma unroll
            for (int ng = 0; ng < 2; ng++) {
                ldsm4(bfh[ng], fa40(bh, wn * 32 + ng * 16, k0, lane));
                ldsm4(bfl[ng], fa40(bl, wn * 32 + ng * 16, k0, lane));
            }
            #pragma unroll
            for (int mi = 0; mi < 2; mi++)
                #pragma unroll
                for (int nj = 0; nj < 4; nj++) {
                    const int ng = nj >> 1, hh = nj & 1;
                    mma16816(acc[mi][nj], afh[mi], bfh[ng][hh], bfh[ng][hh + 2]);
                    mma16816(acc[mi][nj], afh[mi], bfl[ng][hh], bfl[ng][hh + 2]);
                    mma16816(acc[mi][nj], afl[mi], bfh[ng][hh], bfh[ng][hh + 2]);
                }
        }
        __syncthreads();
    }

    #pragma unroll
    for (int mi = 0; mi < 2; mi++)
        #pragma unroll
        for (int half = 0; half < 2; half++) {
            const int m = bm + wm * 32 + mi * 16 + (lane >> 2) + half * 8;
            const int bb = m >> 11, l = m & 2047;
            #pragma unroll
            for (int nj = 0; nj < 4; nj++) {
                const int c = bn + wn * 32 + nj * 8 + (lane & 3) * 2;
                const int h = c >> 6, dd = c & 63;
                const size_t idx =
                    (((size_t)(bb * NH_ + h)) * 2048 + l) * 64 + dd;
                const float v0 = alpha * (acc[mi][nj][half * 2]     + bias[c]);
                const float v1 = alpha * (acc[mi][nj][half * 2 + 1] + bias[c + 1]);
                if (mode == 0) {
                    *(float2*)&dstF[idx] = make_float2(v0, v1);
                } else {
                    uint32_t lo;
                    const uint32_t hi = splitbf2(v0, v1, lo);
                    *(uint32_t*)&dstHi[idx] = hi;
                    *(uint32_t*)&dstLo[idx] = lo;
                }
            }
        }
}

// ---------------------------------------------------------------------------
// V transpose (unchanged).
// ---------------------------------------------------------------------------
__global__ __launch_bounds__(256) void vtrans_kernel()
{
    const int z = blockIdx.y, l0 = blockIdx.x * 64;
    __shared__ float tile[64][65];
    const int t = threadIdx.x, row = t >> 2, q = t & 3;
    #pragma unroll
    for (int i = 0; i < 4; i++) {
        float4 v = *(const float4*)&g_Vf[((size_t)z * 2048 + l0 + row) * 64 + q * 16 + i * 4];
        tile[row][q * 16 + i * 4 + 0] = v.x;
        tile[row][q * 16 + i * 4 + 1] = v.y;
        tile[row][q * 16 + i * 4 + 2] = v.z;
        tile[row][q * 16 + i * 4 + 3] = v.w;
    }
    __syncthreads();
    float v[16];
    #pragma unroll
    for (int i = 0; i < 16; i++) v[i] = tile[q * 16 + i][row];
    uint4 h0, l0v, h1, l1;
    split8(v, h0, l0v); split8(v + 8, h1, l1);
    const size_t base = ((size_t)z * 64 + row) * 2048 + l0 + q * 16;
    *(uint4*)&g_Vthi[base]     = h0;  *(uint4*)&g_Vthi[base + 8] = h1;
    *(uint4*)&g_Vtlo[base]     = l0v; *(uint4*)&g_Vtlo[base + 8] = l1;
}

// ---------------------------------------------------------------------------
// QK^T via bf16x3 mma.sync (round-10/13 + 2-CTA launch bound).
// ---------------------------------------------------------------------------
__global__ __launch_bounds__(512, 2) void qk_mma(
    const int* __restrict__ mask, float* __restrict__ S)
{
    extern __shared__ __align__(16) unsigned short sm[];
    const uint32_t sb = smem_u32(sm);
    const int t = threadIdx.x, lane = t & 31, w = t >> 5;
    const int wm = w >> 2, wn = w & 3;
    const int z = blockIdx.z, bm = blockIdx.y * 128, bn = blockIdx.x * 128;

    const uint32_t qh = sb, ql = sb + 9216*2, kh = sb + 18432*2, kl = sb + 27648*2;

    #pragma unroll
    for (int c = 0; c < 8; c++) {
        const int id   = c * 512 + t;
        const int tile = id >> 10;
        const int row  = (id >> 3) & 127;
        const int seg  = id & 7;
        const __nv_bfloat16* p0 =
            (tile == 0) ? g_Qhi : (tile == 1) ? g_Qlo :
            (tile == 2) ? g_Khi : g_Klo;
        const int rb = (tile < 2) ? bm : bn;
        const __nv_bfloat16* src =
            p0 + ((size_t)z * 2048 + rb + row) * 64 + seg * 8;
        const uint32_t dst = sb + (uint32_t)(tile * 9216 + row * 72 + seg * 8) * 2;
        cpa16(dst, src);
    }
    CP_COMMIT();
    CP_WAIT0();
    __syncthreads();

    float acc[2][4][4];
    #pragma unroll
    for (int i = 0; i < 2; i++)
        #pragma unroll
        for (int j = 0; j < 4; j++)
            #pragma unroll
            for (int q = 0; q < 4; q++) acc[i][j][q] = 0.f;

    #pragma unroll
    for (int k16 = 0; k16 < 4; k16++) {
        const int k0 = k16 * 16;
        uint32_t afh[2][4], afl[2][4], bfh[2][4], bfl[2][4];
        #pragma unroll
        for (int mi = 0; mi < 2; mi++) {
            ldsm4(afh[mi], fa72(qh, wm * 32 + mi * 16, k0, lane));
            ldsm4(afl[mi], fa72(ql, wm * 32 + mi * 16, k0, lane));
        }
        #pragma unroll
        for (int ng = 0; ng < 2; ng++) {
            ldsm4(bfh[ng], fa72(kh, wn * 32 + ng * 16, k0, lane));
            ldsm4(bfl[ng], fa72(kl, wn * 32 + ng * 16, k0, lane));
        }
        #pragma unroll
        for (int mi = 0; mi < 2; mi++)
            #pragma unroll
            for (int nj = 0; nj < 4; nj++) {
                const int ng = nj >> 1, hh = nj & 1;
                mma16816(acc[mi][nj], afh[mi], bfh[ng][hh], bfh[ng][hh + 2]);
                mma16816(acc[mi][nj], afh[mi], bfl[ng][hh], bfl[ng][hh + 2]);
                mma16816(acc[mi][nj], afl[mi], bfh[ng][hh], bfh[ng][hh + 2]);
            }
    }

    float* Sz = S + (size_t)z * LQ_ * LK_;
    float2* part = g_part + ((size_t)z * 64 + blockIdx.x * 4 + wn) * LQ_;
    #pragma unroll
    for (int mi = 0; mi < 2; mi++)
        #pragma unroll
        for (int half = 0; half < 2; half++) {
            const int r = bm + wm * 32 + mi * 16 + (lane >> 2) + half * 8;
            float v[8];
            #pragma unroll
            for (int nj = 0; nj < 4; nj++) {
                const int c = bn + wn * 32 + nj * 8 + (lane & 3) * 2;
                const int2 mm = *(const int2*)&mask[(size_t)r * LK_ + c];
                v[nj * 2]     = mm.x ? acc[mi][nj][half * 2]     : NEGV;
                v[nj * 2 + 1] = mm.y ? acc[mi][nj][half * 2 + 1] : NEGV;
                *(float2*)&Sz[(size_t)r * LK_ + c] =
                    make_float2(v[nj * 2], v[nj * 2 + 1]);
            }
            float mx = v[0];
            #pragma unroll
            for (int j = 1; j < 8; j++) mx = fmaxf(mx, v[j]);
            mx = fmaxf(mx, __shfl_xor_sync(0xffffffffu, mx, 1));
            mx = fmaxf(mx, __shfl_xor_sync(0xffffffffu, mx, 2));
            float smv = 0.f;
            #pragma unroll
            for (int j = 0; j < 8; j++) smv += __expf(v[j] - mx);
            smv += __shfl_xor_sync(0xffffffffu, smv, 1);
            smv += __shfl_xor_sync(0xffffffffu, smv, 2);
            if ((lane & 3) == 0) part[r] = make_float2(mx, smv);
        }
}

// ---------------------------------------------------------------------------
// Combine 64 partial stats per row -> {rowmax, 1/rowsum}.
// ---------------------------------------------------------------------------
__global__ __launch_bounds__(256) void combine_kernel()
{
    const int idx = blockIdx.x * 256 + threadIdx.x;
    if (idx >= NZ * LQ_) return;
    const int z = idx >> 11, m = idx & 2047;
    const float2* p = g_part + (size_t)z * 64 * LQ_ + m;
    float M = -3.4e38f;
    #pragma unroll 8
    for (int i = 0; i < 64; i++) M = fmaxf(M, p[(size_t)i * LQ_].x);
    float Ssum = 0.f;
    #pragma unroll 8
    for (int i = 0; i < 64; i++) {
        const float2 q = p[(size_t)i * LQ_];
        Ssum += q.y * __expf(q.x - M);
    }
    g_stats[idx] = make_float2(M, 1.0f / Ssum);
}

// ---------------------------------------------------------------------------
// PV via bf16x3 mma.sync with register S-prefetch (round-16 + 3-CTA bound).
// ---------------------------------------------------------------------------
#define PV_P(b, h)  ((uint32_t)(((b) * 2 + (h)) * 5120))
#define PV_V(b, h)  ((uint32_t)(20480 + ((b) * 2 + (h)) * 2560))
#define PV_SMEM     ((20480 + 4 * 2560) * 2)

__global__ __launch_bounds__(256, 3) void pv_mma(float* __restrict__ S)
{
    extern __shared__ __align__(16) unsigned short sm[];
    const uint32_t sb = smem_u32(sm);
    const int t = threadIdx.x, lane = t & 31, w = t >> 5;
    const int wm = w >> 1, wn = w & 1;
    const int z = blockIdx.y, bm = blockIdx.x * 128;

    const int r = t >> 1, half = t & 1;
    const float2 st = g_stats[(size_t)z * LQ_ + bm + r];
    float* Sr = S + (size_t)z * LQ_ * LK_ + (size_t)(bm + r) * LK_;

    const __nv_bfloat16* Vh0 = g_Vthi + (size_t)z * 64 * 2048;
    const __nv_bfloat16* Vl0 = g_Vtlo + (size_t)z * 64 * 2048;

    float acc[2][4][4];
    #pragma unroll
    for (int i = 0; i < 2; i++)
        #pragma unroll
        for (int j = 0; j < 4; j++)
            #pragma unroll
            for (int q = 0; q < 4; q++) acc[i][j][q] = 0.f;

    {
        #pragma unroll
        for (int c = 0; c < 2; c++) {
            const int id = c * 256 + t;
            const int hl = id >> 8;
            const int row = (id >> 2) & 63;
            const int seg = id & 3;
            const __nv_bfloat16* src =
                (hl ? Vl0 : Vh0) + (size_t)row * 2048 + 0 + seg * 8;
            cpa16(sb + (PV_V(0, hl) + (uint32_t)(row * 40 + seg * 8)) * 2, src);
        }
        CP_COMMIT();
    }
    float sreg[16];
    {
        const float* sp = Sr + half * 16;
        *(float4*)(sreg)      = *(const float4*)(sp);
        *(float4*)(sreg + 4)  = *(const float4*)(sp + 4);
        *(float4*)(sreg + 8)  = *(const float4*)(sp + 8);
        *(float4*)(sreg + 12) = *(const float4*)(sp + 12);
    }

    for (int it = 0; it < 64; it++) {
        const int kt = it * 32;
        const int pb = it & 1;
        {
            uint4 hi, lo;
            #pragma unroll
            for (int s = 0; s < 2; s++) {
                float v[8];
                #pragma unroll
                for (int j = 0; j < 8; j++)
                    v[j] = __expf(sreg[s * 8 + j] - st.x) * st.y;
                float* sp = Sr + kt + half * 16 + s * 8;
                *(float4*)(sp)     = make_float4(v[0], v[1], v[2], v[3]);
                *(float4*)(sp + 4) = make_float4(v[4], v[5], v[6], v[7]);
                split8(v, hi, lo);
                const uint32_t off = (uint32_t)(r * 40 + half * 16 + s * 8) * 2;
                *(uint4*)((char*)sm + (PV_P(pb, 0)) * 2 + off) = hi;
                *(uint4*)((char*)sm + (PV_P(pb, 1)) * 2 + off) = lo;
            }
        }
        if (it + 1 < 64) {
            const float* sp = Sr + (it + 1) * 32 + half * 16;
            *(float4*)(sreg)      = *(const float4*)(sp);
            *(float4*)(sreg + 4)  = *(const float4*)(sp + 4);
            *(float4*)(sreg + 8)  = *(const float4*)(sp + 8);
            *(float4*)(sreg + 12) = *(const float4*)(sp + 12);
        }
        if (it + 1 < 64) {
            const int vb = (it + 1) & 1;
            const int kn = (it + 1) * 32;
            #pragma unroll
            for (int c = 0; c < 2; c++) {
                const int id = c * 256 + t;
                const int hl = id >> 8;
                const int row = (id >> 2) & 63;
                const int seg = id & 3;
                const __nv_bfloat16* src =
                    (hl ? Vl0 : Vh0) + (size_t)row * 2048 + kn + seg * 8;
                cpa16(sb + (PV_V(vb, hl) + (uint32_t)(row * 40 + seg * 8)) * 2, src);
            }
            CP_COMMIT();
            CP_WAIT1();
        } else {
            CP_WAIT0();
        }
        __syncthreads();

        const uint32_t ph = sb + PV_P(pb, 0) * 2, pl = sb + PV_P(pb, 1) * 2;
        const uint32_t vh = sb + PV_V(pb, 0) * 2, vl = sb + PV_V(pb, 1) * 2;
        #pragma unroll
        for (int k16 = 0; k16 < 2; k16++) {
            const int k0 = k16 * 16;
            uint32_t afh[2][4], afl[2][4], bfh[2][4], bfl[2][4];
            #pragma unroll
            for (int mi = 0; mi < 2; mi++) {
                ldsm4(afh[mi], fa40(ph, wm * 32 + mi * 16, k0, lane));
                ldsm4(afl[mi], fa40(pl, wm * 32 + mi * 16, k0, lane));
            }
            #pragma unroll
            for (int ng = 0; ng < 2; ng++) {
                ldsm4(bfh[ng], fa40(vh, wn * 32 + ng * 16, k0, lane));
                ldsm4(bfl[ng], fa40(vl, wn * 32 + ng * 16, k0, lane));
            }
            #pragma unroll
            for (int mi = 0; mi < 2; mi++)
                #pragma unroll
                for (int nj = 0; nj < 4; nj++) {
                    const int ng = nj >> 1, hh = nj & 1;
                    mma16816(acc[mi][nj], afh[mi], bfh[ng][hh], bfh[ng][hh + 2]);
                    mma16816(acc[mi][nj], afh[mi], bfl[ng][hh], bfl[ng][hh + 2]);
                    mma16816(acc[mi][nj], afl[mi], bfh[ng][hh], bfh[ng][hh + 2]);
                }
        }
        __syncthreads();
    }

    const int bb = z >> 4, h = z & 15;
    #pragma unroll
    for (int mi = 0; mi < 2; mi++)
        #pragma unroll
        for (int nj = 0; nj < 4; nj++) {
            const int r0 = bm + wm * 32 + mi * 16 + (lane >> 2);
            const int c  = wn * 32 + nj * 8 + (lane & 3) * 2;
            #pragma unroll
            for (int hf = 0; hf < 2; hf++) {
                const int rr = r0 + hf * 8;
                const size_t idx = ((size_t)bb * LQ_ + rr) * HDA + h * 64 + c;
                uint32_t lo;
                const uint32_t hi = splitbf2(acc[mi][nj][hf * 2],
                                             acc[mi][nj][hf * 2 + 1], lo);
                *(uint32_t*)&g_Ohhi[idx] = hi;
                *(uint32_t*)&g_Ohlo[idx] = lo;
            }
        }
}

// ---------------------------------------------------------------------------
// Output GEMM via bf16x3 HMMA (round-16 + 2-CTA bound).
// ---------------------------------------------------------------------------
#define OA(b, arr) ((uint32_t)(((b) * 2 + (arr)) * 5120))
#define OB(b, arr) ((uint32_t)(20480 + ((b) * 2 + (arr)) * 2560))
#define O_SMEM     61440

__device__ __forceinline__ void o_load_chunk(
    uint32_t sb, int b, int kt, int t, int bm)
{
    #pragma unroll
    for (int c = 0; c < 3; c++) {
        const int id = c * 512 + t;
        if (id < 1024) {
            const int arr = id >> 9;
            const int row = (id >> 2) & 127;
            const int seg = id & 3;
            const __nv_bfloat16* src =
                (arr ? g_Ohlo : g_Ohhi) + (size_t)(bm + row) * HDA + kt + seg * 8;
            cpa16(sb + (OA(b, arr) + (uint32_t)(row * 40 + seg * 8)) * 2, src);
        } else {
            const int id2 = id - 1024;
            const int arr = id2 >> 8;
            const int row = (id2 >> 2) & 63;
            const int seg = id2 & 3;
            const __nv_bfloat16* src =
                (arr ? g_Wolo : g_Wohi) + (size_t)row * HDA + kt + seg * 8;
            cpa16(sb + (OB(b, arr) + (uint32_t)(row * 40 + seg * 8)) * 2, src);
        }
    }
}

__global__ __launch_bounds__(512, 2) void o_mma(
    const float* __restrict__ bo, float* __restrict__ out)
{
    extern __shared__ __align__(16) unsigned short sm[];
    const uint32_t sb = smem_u32(sm);
    const int t = threadIdx.x, lane = t & 31, w = t >> 5;
    const int wm = w >> 2, wn = w & 3;
    const int bm = blockIdx.x * 128;

    float acc[2][2][4];
    #pragma unroll
    for (int i = 0; i < 2; i++)
        #pragma unroll
        for (int j = 0; j < 2; j++)
            #pragma unroll
            for (int q = 0; q < 4; q++) acc[i][j][q] = 0.f;

    o_load_chunk(sb, 0, 0, t, bm);
    CP_COMMIT();

    for (int it = 0; it < 32; it++) {
        if (it + 1 < 32) {
            o_load_chunk(sb, (it + 1) & 1, (it + 1) * 32, t, bm);
            CP_COMMIT();
            CP_WAIT1();
        } else {
            CP_WAIT0();
        }
        __syncthreads();
        const int b = it & 1;
        const uint32_t ah = sb + OA(b, 0) * 2, al = sb + OA(b, 1) * 2;
        const uint32_t bh = sb + OB(b, 0) * 2, bl = sb + OB(b, 1) * 2;
        #pragma unroll
        for (int k16 = 0; k16 < 2; k16++) {
            const int k0 = k16 * 16;
            uint32_t afh[2][4], afl[2][4], bfh[4], bfl[4];
            #pragma unroll
            for (int mi = 0; mi < 2; mi++) {
                ldsm4(afh[mi], fa40(ah, wm * 32 + mi * 16, k0, lane));
                ldsm4(afl[mi], fa40(al, wm * 32 + mi * 16, k0, lane));
            }
            ldsm4(bfh, fa40(bh, wn * 16, k0, lane));
            ldsm4(bfl, fa40(bl, wn * 16, k0, lane));
            #pragma unroll
            for (int mi = 0; mi < 2; mi++)
                #pragma unroll
                for (int nj = 0; nj < 2; nj++) {
                    mma16816(acc[mi][nj], afh[mi], bfh[nj], bfh[nj + 2]);
                    mma16816(acc[mi][nj], afh[mi], bfl[nj], bfl[nj + 2]);
                    mma16816(acc[mi][nj], afl[mi], bfh[nj], bfh[nj + 2]);
                }
        }
        __syncthreads();
    }

    #pragma unroll
    for (int mi = 0; mi < 2; mi++)
        #pragma unroll
        for (int hf = 0; hf < 2; hf++) {
            const int m = bm + wm * 32 + mi * 16 + (lane >> 2) + hf * 8;
            #pragma unroll
            for (int nj = 0; nj < 2; nj++) {
                const int c = wn * 16 + nj * 8 + (lane & 3) * 2;
                *(float2*)&out[(size_t)m * HD_ + c] = make_float2(
                    acc[mi][nj][hf * 2]     + bo[c],
                    acc[mi][nj][hf * 2 + 1] + bo[c + 1]);
            }
        }
}

// ---------------------------------------------------------------------------
extern "C" void kernel_launch(void* const* d_in, const int* in_sizes, int n_in,
                              void* d_out, int out_size)
{
    (void)in_sizes; (void)n_in; (void)out_size;
    const float* q    = (const float*)d_in[0];
    const float* k    = (const float*)d_in[1];
    const float* v    = (const float*)d_in[2];
    const int*   mask = (const int*)  d_in[3];
    const float* wq   = (const float*)d_in[4];
    const float* bq   = (const float*)d_in[5];
    const float* wk   = (const float*)d_in[6];
    const float* bk   = (const float*)d_in[7];
    const float* wv   = (const float*)d_in[8];
    const float* bv   = (const float*)d_in[9];
    const float* wo   = (const float*)d_in[10];
    const float* bo   = (const float*)d_in[11];

    float* out    = (float*)d_out;                       // [B, LQ, 64]
    float* scores = out + (size_t)B_ * LQ_ * HD_;        // [B, H, LQ, LK]

    __nv_bfloat16 *Xhi, *Xlo, *Whi, *Wlo, *Qhi, *Qlo, *Khi, *Klo, *Wohi, *Wolo;
    float* Vf;
    cudaGetSymbolAddress((void**)&Xhi, g_Xhi);
    cudaGetSymbolAddress((void**)&Xlo, g_Xlo);
    cudaGetSymbolAddress((void**)&Whi, g_Whi);
    cudaGetSymbolAddress((void**)&Wlo, g_Wlo);
    cudaGetSymbolAddress((void**)&Qhi, g_Qhi);
    cudaGetSymbolAddress((void**)&Qlo, g_Qlo);
    cudaGetSymbolAddress((void**)&Khi, g_Khi);
    cudaGetSymbolAddress((void**)&Klo, g_Klo);
    cudaGetSymbolAddress((void**)&Wohi, g_Wohi);
    cudaGetSymbolAddress((void**)&Wolo, g_Wolo);
    cudaGetSymbolAddress((void**)&Vf,  g_Vf);

    const int QK_SMEM = 4 * 128 * 72 * 2;                // 73728 B
    cudaFuncSetAttribute(qk_mma, cudaFuncAttributeMaxDynamicSharedMemorySize,
                         QK_SMEM);
    cudaFuncSetAttribute(pv_mma, cudaFuncAttributeMaxDynamicSharedMemorySize,
                         PV_SMEM);
    cudaFuncSetAttribute(proj_mma, cudaFuncAttributeMaxDynamicSharedMemorySize,
                         PJ_SMEM);
    cudaFuncSetAttribute(o_mma, cudaFuncAttributeMaxDynamicSharedMemorySize,
                         O_SMEM);

    const dim3 blk(256);
    const int  NX8 = (B_ * LQ_ * IND) / 8;
    const int  NW8 = (IND * IND) / 8;
    const int  NWO8 = (HD_ * HDA) / 8;                   // 8192
    const dim3 gproj(IND / 128, (B_ * LQ_) / 128);       // (8, 64)

    split_kernel<<<NX8 / 256, blk>>>(q, Xhi, Xlo, NX8);
    split_kernel<<<NW8 / 256, blk>>>(wq, Whi, Wlo, NW8);
    proj_mma<<<gproj, 512, PJ_SMEM>>>(bq, 0.125f, 1, nullptr, Qhi, Qlo);
    split_kernel<<<NX8 / 256, blk>>>(k, Xhi, Xlo, NX8);
    split_kernel<<<NW8 / 256, blk>>>(wk, Whi, Wlo, NW8);
    proj_mma<<<gproj, 512, PJ_SMEM>>>(bk, 1.0f, 1, nullptr, Khi, Klo);
    split_kernel<<<NX8 / 256, blk>>>(v, Xhi, Xlo, NX8);
    split_kernel<<<NW8 / 256, blk>>>(wv, Whi, Wlo, NW8);
    proj_mma<<<gproj, 512, PJ_SMEM>>>(bv, 1.0f, 0, Vf, nullptr, nullptr);

    split_kernel<<<NWO8 / 256, blk>>>(wo, Wohi, Wolo, NWO8);

    vtrans_kernel<<<dim3(LK_ / 64, NZ), blk>>>();        // (32, 64)

    qk_mma<<<dim3(LK_ / 128, LQ_ / 128, NZ), 512, QK_SMEM>>>(mask, scores);

    combine_kernel<<<(NZ * LQ_ + 255) / 256, blk>>>();   // 512 blocks

    pv_mma<<<dim3(LQ_ / 128, NZ), blk, PV_SMEM>>>(scores);

    o_mma<<<(B_ * LQ_) / 128, 512, O_SMEM>>>(bo, out);   // 64 blocks
}